// round 15
// baseline (speedup 1.0000x reference)
#include <cuda_runtime.h>
#include <cuda_fp16.h>
#include <math.h>
#include <stdint.h>

#define HW 65536
#define NBUF (2*256*HW)

// ---------------- static scratch ----------------
__device__ __half g_Xh[NBUF];       // x [b][px][c]
__device__ __half g_Hc1[NBUF];      // conv_iem out [r][c]
__device__ __half g_Hc2[NBUF];      // conv_nem out [r][c]
__device__ __half g_Hd1[NBUF];      // illum map [r][c]
__device__ __half g_Hd2[NBUF];      // noise map [r][c]
__device__ __half g_Ha[NBUF];       // attn out [r][c]
__device__ __half g_wct[2*589824];  // conv weights [m][tap][oc][c]
__device__ __half g_wt4[4*65536];   // 1x1 weights [m][oc][c]
__device__ float  g_part[1048576];  // bn partials [2][1024 cta][2][256 ch]
__device__ float  g_part2[32768];   // bn partials lvl2
__device__ float  g_bna[512];
__device__ float  g_bnc[512];
__device__ float  g_is[2*HW];
__device__ float  g_ns[2*HW];

// ---------------- helpers ----------------
__device__ __forceinline__ uint32_t smem_u32(const void* p) {
    uint32_t a;
    asm("{ .reg .u64 t; cvta.to.shared.u64 t, %1; cvt.u32.u64 %0, t; }" : "=r"(a) : "l"(p));
    return a;
}
__device__ __forceinline__ uint32_t f2h2(float a, float b) {
    __half2 h = __floats2half2_rn(a, b);
    return *(uint32_t*)&h;
}
__device__ __forceinline__ void h8_to_f(uint4 t, float* f) {
    const __half2* hp = (const __half2*)&t;
#pragma unroll
    for (int u = 0; u < 4; u++) {
        float2 ff = __half22float2(hp[u]);
        f[2*u] = ff.x; f[2*u+1] = ff.y;
    }
}
__device__ __forceinline__ void cpa16(uint32_t s, const void* g, uint32_t n) {
    asm volatile("cp.async.cg.shared.global [%0], [%1], 16, %2;"
                 :: "r"(s), "l"(g), "r"(n) : "memory");
}
#define CP_COMMIT()  asm volatile("cp.async.commit_group;" ::: "memory")
#define CP_WAIT2()   asm volatile("cp.async.wait_group 2;" ::: "memory")
#define CP_WAIT1()   asm volatile("cp.async.wait_group 1;" ::: "memory")
#define CP_WAIT0()   asm volatile("cp.async.wait_group 0;" ::: "memory")

__device__ __forceinline__ void mma16(float* d, const uint32_t* a, const uint32_t* b) {
    asm volatile("mma.sync.aligned.m16n8k16.row.col.f32.f16.f16.f32 "
        "{%0,%1,%2,%3}, {%4,%5,%6,%7}, {%8,%9}, {%0,%1,%2,%3};"
        : "+f"(d[0]), "+f"(d[1]), "+f"(d[2]), "+f"(d[3])
        : "r"(a[0]), "r"(a[1]), "r"(a[2]), "r"(a[3]), "r"(b[0]), "r"(b[1]));
}
__device__ __forceinline__ void ldsm4(uint32_t* r, uint32_t a) {
    asm volatile("ldmatrix.sync.aligned.m8n8.x4.shared.b16 {%0,%1,%2,%3}, [%4];"
        : "=r"(r[0]), "=r"(r[1]), "=r"(r[2]), "=r"(r[3]) : "r"(a));
}

// ---------------- weight prep ----------------
__global__ void tconv_kernel(const float* __restrict__ w0, const float* __restrict__ w1,
                             __half* __restrict__ out) {
    int i = blockIdx.x * 256 + threadIdx.x;
    int m = i / 589824;
    int r = i - m * 589824;
    int tap = r >> 16;
    int rem = r & 65535;
    int oc  = rem >> 8;
    int c   = rem & 255;
    const float* w = m ? w1 : w0;
    out[i] = __float2half_rn(w[oc * 2304 + c * 9 + tap]);
}

__global__ void t1x1_kernel(const float* __restrict__ wq, const float* __restrict__ wk,
                            const float* __restrict__ wv, const float* __restrict__ wp,
                            __half* __restrict__ out) {
    int i = blockIdx.x * 256 + threadIdx.x;
    int m = i >> 16;
    int r = i & 65535;
    int o = r >> 8;
    int c = r & 255;
    const float* w = (m == 0) ? wq : (m == 1) ? wk : (m == 2) ? wv : wp;
    out[i] = __float2half_rn(w[o * 256 + c]);
}

// ---------------- x transpose: NCHW -> [b][px][c] fp16 ----------------
__global__ void xT_kernel(const float* __restrict__ x, __half* __restrict__ xT) {
    __shared__ float t[32][33];
    int b  = blockIdx.z;
    int c0 = blockIdx.y * 32;
    int p0 = blockIdx.x * 32;
    int tx = threadIdx.x, ty = threadIdx.y;
    t[ty][tx] = x[(((size_t)((b << 8) + c0 + ty)) << 16) + p0 + tx];
    __syncthreads();
    xT[(((size_t)((b << 16) + p0 + ty)) << 8) + c0 + tx] = __float2half_rn(t[tx][ty]);
}

// ---------------- 3x3 conv implicit GEMM, BN partials fused ----------------
#define CONV_XS_B  8704
#define CONV_STG_B 33280
__global__ void __launch_bounds__(256, 2) conv_mma(const __half* __restrict__ xT,
                                                   const __half* __restrict__ W2base,
                                                   __half* __restrict__ out1,
                                                   __half* __restrict__ out2,
                                                   float* __restrict__ part) {
    extern __shared__ char smc[];
    const int tid  = threadIdx.x;
    const int w    = tid >> 5, lane = tid & 31;
    const int g    = lane >> 2, tg = lane & 3;
    const int y    = blockIdx.x >> 1;
    const int p0   = (blockIdx.x & 1) << 7;
    const int oc0  = blockIdx.y << 7;
    const int m    = blockIdx.z >> 1;
    const int b    = blockIdx.z & 1;
    const __half* W2 = W2base + (size_t)m * 589824;
    __half* out = m ? out2 : out1;
    const int wm   = w >> 2, wn = w & 3;
    const uint32_t sm_u = smem_u32(smc);
    const int aRowB = wm * 64 + (lane & 15);
    const int bRowB = wn * 32 + ((lane >> 4) << 3) + (lane & 7);
    const uint32_t aQ = (uint32_t)(lane >> 4);
    const uint32_t bQ = (uint32_t)((lane >> 3) & 1);

    float acc[4][4][4];
#pragma unroll
    for (int mi = 0; mi < 4; mi++)
#pragma unroll
        for (int ni = 0; ni < 4; ni++)
#pragma unroll
            for (int r = 0; r < 4; r++) acc[mi][ni][r] = 0.f;

    auto do_load = [&](int step, int buf) {
        int cc = step / 3;
        int ky = step - cc * 3;
        int c0 = cc * 32;
        uint32_t xs = sm_u + buf * CONV_STG_B;
        uint32_t ws = xs + CONV_XS_B;
        int yin = y + ky - 1;
        bool yok = (unsigned)yin < 256u;
#pragma unroll
        for (int jj = 0; jj < 3; jj++) {
            int j = jj * 256 + tid;
            if (j < 520) {
                int r = j >> 2, q = j & 3;
                int xin = p0 + r - 1;
                bool ok = yok && ((unsigned)xin < 256u);
                const __half* src = ok
                    ? xT + ((((size_t)b << 16) + ((size_t)yin << 8) + xin) << 8) + c0 + q * 8
                    : xT;
                cpa16(xs + r * 64 + ((q ^ ((r >> 1) & 3)) << 4), src, ok ? 16u : 0u);
            }
        }
#pragma unroll
        for (int jj = 0; jj < 6; jj++) {
            int j = jj * 256 + tid;
            int row = j >> 2, q = j & 3;
            int kx = row >> 7, oc = row & 127;
            int tap = ky * 3 + kx;
            cpa16(ws + row * 64 + ((q ^ ((row >> 1) & 3)) << 4),
                  W2 + (((size_t)(tap * 256 + oc0 + oc)) << 8) + c0 + q * 8, 16u);
        }
        CP_COMMIT();
    };

    auto do_compute = [&](int buf) {
        uint32_t xs = sm_u + buf * CONV_STG_B;
        uint32_t ws = xs + CONV_XS_B;
#pragma unroll
        for (int kx = 0; kx < 3; kx++) {
#pragma unroll
            for (int ks = 0; ks < 2; ks++) {
                uint32_t af[4][4];
#pragma unroll
                for (int mi = 0; mi < 4; mi++) {
                    int row = aRowB + mi * 16 + kx;
                    uint32_t q = (uint32_t)(ks * 2) + aQ;
                    ldsm4(af[mi], xs + row * 64 + ((q ^ ((row >> 1) & 3)) << 4));
                }
                uint32_t bf[4][2];
#pragma unroll
                for (int pn = 0; pn < 2; pn++) {
                    int row = kx * 128 + bRowB + pn * 16;
                    uint32_t q = (uint32_t)(ks * 2) + bQ;
                    uint32_t t[4];
                    ldsm4(t, ws + row * 64 + ((q ^ ((row >> 1) & 3)) << 4));
                    bf[2*pn][0]   = t[0]; bf[2*pn][1]   = t[1];
                    bf[2*pn+1][0] = t[2]; bf[2*pn+1][1] = t[3];
                }
#pragma unroll
                for (int mi = 0; mi < 4; mi++)
#pragma unroll
                    for (int ni = 0; ni < 4; ni++)
                        mma16(acc[mi][ni], af[mi], bf[ni]);
            }
        }
    };

    do_load(0, 0);
    do_load(1, 1);
    for (int s = 0; s < 24; s++) {
        if (s < 23) { CP_WAIT1(); } else { CP_WAIT0(); }
        __syncthreads();
        if (s + 2 < 24) do_load(s + 2, (s + 2) % 3);
        do_compute(s % 3);
    }
    __syncthreads();

    float* S = (float*)smc;
#pragma unroll
    for (int mi = 0; mi < 4; mi++) {
        int px = wm * 64 + mi * 16 + g;
#pragma unroll
        for (int ni = 0; ni < 4; ni++) {
            int oc = wn * 32 + ni * 8 + 2 * tg;
            S[px * 132 + oc]           = acc[mi][ni][0];
            S[px * 132 + oc + 1]       = acc[mi][ni][1];
            S[(px + 8) * 132 + oc]     = acc[mi][ni][2];
            S[(px + 8) * 132 + oc + 1] = acc[mi][ni][3];
        }
    }
    __syncthreads();
#pragma unroll
    for (int it = 0; it < 16; it++) {
        int px = w + it * 8;
        float4 v = *(float4*)&S[px * 132 + lane * 4];
        uint2 o;
        o.x = f2h2(v.x, v.y);
        o.y = f2h2(v.z, v.w);
        *(uint2*)(out + (((size_t)((b << 16) + (y << 8) + p0 + px)) << 8) + oc0 + lane * 4) = o;
    }
    float* R = (float*)(smc + 67584);
    {
        int ocl = tid & 127, half = tid >> 7;
        float s = 0.f, s2 = 0.f;
#pragma unroll 8
        for (int px = 0; px < 64; px++) {
            float v = S[(half * 64 + px) * 132 + ocl];
            s += v; s2 = fmaf(v, v, s2);
        }
        R[(half * 128 + ocl) * 2]     = s;
        R[(half * 128 + ocl) * 2 + 1] = s2;
    }
    __syncthreads();
    if (tid < 128) {
        float s  = R[tid * 2]     + R[(128 + tid) * 2];
        float s2 = R[tid * 2 + 1] + R[(128 + tid) * 2 + 1];
        size_t base = ((size_t)(m * 1024 + b * 512 + blockIdx.x) * 2) * 256 + oc0 + tid;
        part[base]       = s;
        part[base + 256] = s2;
    }
}

// ---------------- BN stats: two-stage parallel reduce ----------------
__global__ void bnstats2a(const float* __restrict__ part, float* __restrict__ part2) {
    int m = blockIdx.x, chunk = blockIdx.y;
    int c = threadIdx.x;
    float s = 0.f, s2 = 0.f;
    for (int r = 0; r < 32; r++) {
        size_t base = ((size_t)(m * 1024 + chunk * 32 + r) * 2) * 256;
        s  += part[base + c];
        s2 += part[base + 256 + c];
    }
    size_t ob = ((size_t)(m * 32 + chunk) * 2) * 256;
    part2[ob + c]       = s;
    part2[ob + 256 + c] = s2;
}

__global__ void bnstats2b(const float* __restrict__ part2,
                          const float* __restrict__ g1, const float* __restrict__ b1,
                          const float* __restrict__ g2, const float* __restrict__ b2,
                          float* __restrict__ pa, float* __restrict__ pc) {
    int m = blockIdx.x;
    const float* gamma = m ? g2 : g1;
    const float* beta  = m ? b2 : b1;
    int c = threadIdx.x;
    float s = 0.f, s2 = 0.f;
    for (int r = 0; r < 32; r++) {
        size_t base = ((size_t)(m * 32 + r) * 2) * 256;
        s  += part2[base + c];
        s2 += part2[base + 256 + c];
    }
    float mean = s  * (1.f / 131072.f);
    float var  = s2 * (1.f / 131072.f) - mean * mean;
    float a = gamma[c] * rsqrtf(var + 1e-5f);
    pa[m * 256 + c] = a;
    pc[m * 256 + c] = beta[c] - mean * a;
}

// ---------------- depthwise conv pair (half2, 2ch x 2px, mean fused) ----------------
__global__ void __launch_bounds__(128) dwconv_t(
                         const __half* __restrict__ in1, const __half* __restrict__ in2,
                         const float* __restrict__ pa, const float* __restrict__ pc,
                         const float* __restrict__ wd1, const float* __restrict__ wd2,
                         __half* __restrict__ out1, __half* __restrict__ out2,
                         float* __restrict__ mean1, float* __restrict__ mean2) {
    __shared__ float red0[4], red1[4];
    int m = blockIdx.y;
    const __half* in  = m ? in2 : in1;
    const float*  wdw = m ? wd2 : wd1;
    __half* out       = m ? out2 : out1;
    float* mean_out   = m ? mean2 : mean1;
    int j = blockIdx.x;
    int c2 = threadIdx.x;
    int r0 = j << 1;
    int p  = r0 & 65535;
    int y = p >> 8, xx = p & 255;
    size_t bb = (size_t)(r0 - p) << 8;
    float a0 = pa[m * 256 + 2 * c2],     cb0 = pc[m * 256 + 2 * c2];
    float a1 = pa[m * 256 + 2 * c2 + 1], cb1 = pc[m * 256 + 2 * c2 + 1];
    float w0[9], w1[9];
#pragma unroll
    for (int t = 0; t < 9; t++) {
        w0[t] = wdw[(2 * c2) * 9 + t];
        w1[t] = wdw[(2 * c2 + 1) * 9 + t];
    }
    float accA0 = 0.f, accA1 = 0.f, accB0 = 0.f, accB1 = 0.f;
#pragma unroll
    for (int ky = 0; ky < 3; ky++) {
        int yy = y + ky - 1;
        if ((unsigned)yy >= 256u) continue;
        float v0[4], v1[4];
#pragma unroll
        for (int dx = 0; dx < 4; dx++) {
            int xv = xx + dx - 1;
            bool ok = (unsigned)xv < 256u;
            float2 f = {0.f, 0.f};
            if (ok) {
                __half2 hv = *(const __half2*)(in + (bb + (size_t)((yy << 8) + xv) * 256) + 2 * c2);
                f = __half22float2(hv);
            }
            float t0 = fminf(fmaxf(f.x * a0 + cb0, 0.f), 6.f);
            float t1 = fminf(fmaxf(f.y * a1 + cb1, 0.f), 6.f);
            v0[dx] = ok ? t0 : 0.f;
            v1[dx] = ok ? t1 : 0.f;
        }
        accA0 = fmaf(w0[ky*3+0], v0[0], accA0); accA0 = fmaf(w0[ky*3+1], v0[1], accA0); accA0 = fmaf(w0[ky*3+2], v0[2], accA0);
        accA1 = fmaf(w1[ky*3+0], v1[0], accA1); accA1 = fmaf(w1[ky*3+1], v1[1], accA1); accA1 = fmaf(w1[ky*3+2], v1[2], accA1);
        accB0 = fmaf(w0[ky*3+0], v0[1], accB0); accB0 = fmaf(w0[ky*3+1], v0[2], accB0); accB0 = fmaf(w0[ky*3+2], v0[3], accB0);
        accB1 = fmaf(w1[ky*3+0], v1[1], accB1); accB1 = fmaf(w1[ky*3+1], v1[2], accB1); accB1 = fmaf(w1[ky*3+2], v1[3], accB1);
    }
    *(__half2*)(out + (size_t)r0 * 256 + 2 * c2)       = __floats2half2_rn(accA0, accA1);
    *(__half2*)(out + (size_t)(r0 + 1) * 256 + 2 * c2) = __floats2half2_rn(accB0, accB1);

    float s0 = accA0 + accA1, s1 = accB0 + accB1;
#pragma unroll
    for (int off = 16; off; off >>= 1) {
        s0 += __shfl_xor_sync(0xffffffffu, s0, off);
        s1 += __shfl_xor_sync(0xffffffffu, s1, off);
    }
    if ((c2 & 31) == 0) { red0[c2 >> 5] = s0; red1[c2 >> 5] = s1; }
    __syncthreads();
    if (c2 < 4) {
        float t0 = red0[c2], t1 = red1[c2];
#pragma unroll
        for (int off = 2; off; off >>= 1) {
            t0 += __shfl_xor_sync(0xfu, t0, off);
            t1 += __shfl_xor_sync(0xfu, t1, off);
        }
        if (c2 == 0) {
            mean_out[r0]     = t0 * (1.f / 256.f);
            mean_out[r0 + 1] = t1 * (1.f / 256.f);
        }
    }
}

// ---------------- fused q/k/v GEMM + windowed attention ----------------
// grid (1024 windows, 2 batch); 256 threads; 1 CTA/SM; smem 169984 B.
// Layout: Qs[64][264h]@0, Ks@33792, Vt[256][72h]@67584, muls@104448, stages@108544.
#define FQ_KS   33792
#define FQ_VT   67584
#define FQ_MU   104448
#define FQ_STG  108544
#define FQ_SSZ  20480
__global__ void __launch_bounds__(256) fused_qkv_attn(
        const __half* __restrict__ wtb,
        const __half* __restrict__ inQ, const __half* __restrict__ inK,
        const __half* __restrict__ inV,
        const float* __restrict__ is, const float* __restrict__ ns,
        const float* __restrict__ temp,
        __half* __restrict__ outA) {
    extern __shared__ char smc[];
    const int tid  = threadIdx.x;
    const int w    = tid >> 5, lane = tid & 31;
    const int g    = lane >> 2, tg = lane & 3;
    const int win  = blockIdx.x;
    const int b    = blockIdx.y;
    const int wy   = win >> 5, wx = win & 31;
    const int wm   = w >> 1, wn = w & 1;     // GEMM warp tile: 16px x 128oc
    const uint32_t sm_u = smem_u32(smc);
    const int pxbase = (b << 16) + ((wy * 8) << 8) + wx * 8;   // global px of row 0

    // ---- phase 1: q,k,v GEMMs (24 steps: mat = s/8, chunk = s%8) ----
    auto do_load = [&](int step, int buf) {
        int mat = step >> 3;
        int cc  = step & 7;
        int c0  = cc * 32;
        const __half* in = (mat == 0) ? inQ : (mat == 1) ? inK : inV;
        const __half* wt = wtb + (size_t)mat * 65536;
        uint32_t xs = sm_u + FQ_STG + buf * FQ_SSZ;
        uint32_t ws = xs + 4096;
        {
            int r = tid >> 2, q = tid & 3;                    // A: 64 rows
            int gpx = pxbase + ((r >> 3) << 8) + (r & 7);
            cpa16(xs + r * 64 + ((q ^ ((r >> 1) & 3)) << 4),
                  in + (size_t)gpx * 256 + c0 + q * 8, 16u);
        }
#pragma unroll
        for (int jj = 0; jj < 4; jj++) {                      // W: 256 rows
            int j = jj * 256 + tid;
            int r = j >> 2, q = j & 3;
            cpa16(ws + r * 64 + ((q ^ ((r >> 1) & 3)) << 4),
                  wt + (size_t)r * 256 + c0 + q * 8, 16u);
        }
        CP_COMMIT();
    };

    float acc[16][4];
#pragma unroll
    for (int ni = 0; ni < 16; ni++)
#pragma unroll
        for (int r = 0; r < 4; r++) acc[ni][r] = 0.f;

    const int aRow = wm * 16 + (lane & 15);
    const uint32_t aQ = (uint32_t)(lane >> 4);
    const int bRowB = wn * 128 + ((lane >> 4) << 3) + (lane & 7);
    const uint32_t bQ = (uint32_t)((lane >> 3) & 1);

    do_load(0, 0);
    do_load(1, 1);
    for (int s = 0; s < 24; s++) {
        if (s < 23) { CP_WAIT1(); } else { CP_WAIT0(); }
        __syncthreads();
        if (s + 2 < 24) do_load(s + 2, (s + 2) % 3);
        uint32_t xs = sm_u + FQ_STG + (s % 3) * FQ_SSZ;
        uint32_t ws = xs + 4096;
#pragma unroll
        for (int ks = 0; ks < 2; ks++) {
            uint32_t af[4];
            uint32_t q = (uint32_t)(ks * 2) + aQ;
            ldsm4(af, xs + aRow * 64 + ((q ^ ((aRow >> 1) & 3)) << 4));
#pragma unroll
            for (int pn = 0; pn < 8; pn++) {
                int row = bRowB + pn * 16;
                uint32_t qb = (uint32_t)(ks * 2) + bQ;
                uint32_t t[4];
                ldsm4(t, ws + row * 64 + ((qb ^ ((row >> 1) & 3)) << 4));
                mma16(acc[2*pn],     af, t);
                mma16(acc[2*pn + 1], af, t + 2);
            }
        }
        if ((s & 7) == 7) {
            // epilogue for matrix mat = s>>3
            int mat = s >> 3;
            int px0 = wm * 16 + g;
            if (mat < 2) {
                __half* Q = (__half*)(smc + (mat ? FQ_KS : 0));
#pragma unroll
                for (int ni = 0; ni < 16; ni++) {
                    int oc = wn * 128 + ni * 8 + 2 * tg;
                    *(uint32_t*)(Q + px0 * 264 + oc)       = f2h2(acc[ni][0], acc[ni][1]);
                    *(uint32_t*)(Q + (px0 + 8) * 264 + oc) = f2h2(acc[ni][2], acc[ni][3]);
                }
            } else {
                __half* Vt = (__half*)(smc + FQ_VT);          // [256 ch][72 px]
#pragma unroll
                for (int ni = 0; ni < 16; ni++) {
                    int oc = wn * 128 + ni * 8 + 2 * tg;
                    Vt[oc * 72 + px0]           = __float2half_rn(acc[ni][0]);
                    Vt[(oc + 1) * 72 + px0]     = __float2half_rn(acc[ni][1]);
                    Vt[oc * 72 + px0 + 8]       = __float2half_rn(acc[ni][2]);
                    Vt[(oc + 1) * 72 + px0 + 8] = __float2half_rn(acc[ni][3]);
                }
            }
#pragma unroll
            for (int ni = 0; ni < 16; ni++)
#pragma unroll
                for (int r = 0; r < 4; r++) acc[ni][r] = 0.f;
        }
    }
    __syncthreads();

    // ---- phase 2: per-(px,head) scale factors ----
    float* qmul = (float*)(smc + FQ_MU);
    float* kmul = qmul + 512;
    {
        const __half* Q = (const __half*)smc;
        const __half* K = (const __half*)(smc + FQ_KS);
#pragma unroll
        for (int uu = 0; uu < 2; uu++) {
            int u = tid + uu * 256;
            int px = u >> 3, h = u & 7;
            int gpx = pxbase + ((px >> 3) << 8) + (px & 7);
            float qn = 0.f, kn = 0.f;
            const __half2* qr = (const __half2*)(Q + px * 264 + h * 32);
            const __half2* kr = (const __half2*)(K + px * 264 + h * 32);
#pragma unroll
            for (int d = 0; d < 16; d++) {
                float2 fq = __half22float2(qr[d]);
                float2 fk = __half22float2(kr[d]);
                qn = fmaf(fq.x, fq.x, qn); qn = fmaf(fq.y, fq.y, qn);
                kn = fmaf(fk.x, fk.x, kn); kn = fmaf(fk.y, fk.y, kn);
            }
            float nsv = ns[gpx];
            kmul[u] = fminf(fmaxf(1.f - nsv, 0.f), 1.f) / fmaxf(sqrtf(kn), 1e-12f);
            qmul[u] = (1.f + is[gpx]) / fmaxf(sqrtf(qn), 1e-12f)
                    * 0.17677669529663687f * temp[h];
        }
    }
    __syncthreads();

    // ---- phase 3: attention, warp = head ----
    const int h = w;
    const uint32_t qs_u = sm_u;
    const uint32_t ks_u = sm_u + FQ_KS;
    const uint32_t vt_u = sm_u + FQ_VT;
    __half* Os = (__half*)(smc + FQ_STG);   // reuse stage area [64][264]

#pragma unroll
    for (int mh = 0; mh < 2; mh++) {
        float s[2][8][4];
#pragma unroll
        for (int mi = 0; mi < 2; mi++)
#pragma unroll
            for (int ni = 0; ni < 8; ni++)
#pragma unroll
                for (int r = 0; r < 4; r++) s[mi][ni][r] = 0.f;
        // QK^T (raw)
#pragma unroll
        for (int ks = 0; ks < 2; ks++) {
            uint32_t bfr[8][2];
#pragma unroll
            for (int pn = 0; pn < 4; pn++) {
                uint32_t t[4];
                ldsm4(t, ks_u + (pn * 16 + ((lane >> 4) << 3) + (lane & 7)) * 528
                         + (h * 32 + ks * 16) * 2 + ((lane >> 3) & 1) * 16);
                bfr[2*pn][0]   = t[0]; bfr[2*pn][1]   = t[1];
                bfr[2*pn+1][0] = t[2]; bfr[2*pn+1][1] = t[3];
            }
#pragma unroll
            for (int mi = 0; mi < 2; mi++) {
                uint32_t af[4];
                ldsm4(af, qs_u + (mh * 32 + mi * 16 + (lane & 15)) * 528
                          + (h * 32 + ks * 16) * 2 + (lane >> 4) * 16);
#pragma unroll
                for (int ni = 0; ni < 8; ni++)
                    mma16(s[mi][ni], af, bfr[ni]);
            }
        }
        // rank-1 scale + softmax per m16 tile
        float inv[2][2];
#pragma unroll
        for (int mi = 0; mi < 2; mi++) {
            int i0 = mh * 32 + mi * 16 + g;
            float qm0 = qmul[i0 * 8 + h], qm1 = qmul[(i0 + 8) * 8 + h];
#pragma unroll
            for (int ni = 0; ni < 8; ni++) {
                int j0 = ni * 8 + 2 * tg;
                float km0 = kmul[j0 * 8 + h], km1 = kmul[(j0 + 1) * 8 + h];
                s[mi][ni][0] *= qm0 * km0;
                s[mi][ni][1] *= qm0 * km1;
                s[mi][ni][2] *= qm1 * km0;
                s[mi][ni][3] *= qm1 * km1;
            }
            float mx0 = -1e30f, mx1 = -1e30f;
#pragma unroll
            for (int ni = 0; ni < 8; ni++) {
                mx0 = fmaxf(mx0, fmaxf(s[mi][ni][0], s[mi][ni][1]));
                mx1 = fmaxf(mx1, fmaxf(s[mi][ni][2], s[mi][ni][3]));
            }
            mx0 = fmaxf(mx0, __shfl_xor_sync(0xffffffffu, mx0, 1));
            mx0 = fmaxf(mx0, __shfl_xor_sync(0xffffffffu, mx0, 2));
            mx1 = fmaxf(mx1, __shfl_xor_sync(0xffffffffu, mx1, 1));
            mx1 = fmaxf(mx1, __shfl_xor_sync(0xffffffffu, mx1, 2));
            float sum0 = 0.f, sum1 = 0.f;
#pragma unroll
            for (int ni = 0; ni < 8; ni++) {
                s[mi][ni][0] = __expf(s[mi][ni][0] - mx0);
                s[mi][ni][1] = __expf(s[mi][ni][1] - mx0);
                s[mi][ni][2] = __expf(s[mi][ni][2] - mx1);
                s[mi][ni][3] = __expf(s[mi][ni][3] - mx1);
                sum0 += s[mi][ni][0] + s[mi][ni][1];
                sum1 += s[mi][ni][2] + s[mi][ni][3];
            }
            sum0 += __shfl_xor_sync(0xffffffffu, sum0, 1);
            sum0 += __shfl_xor_sync(0xffffffffu, sum0, 2);
            sum1 += __shfl_xor_sync(0xffffffffu, sum1, 1);
            sum1 += __shfl_xor_sync(0xffffffffu, sum1, 2);
            inv[mi][0] = 1.f / sum0;
            inv[mi][1] = 1.f / sum1;
        }
        // P x V
#pragma unroll
        for (int mi = 0; mi < 2; mi++) {
            float o[4][4];
#pragma unroll
            for (int nd = 0; nd < 4; nd++)
#pragma unroll
                for (int r = 0; r < 4; r++) o[nd][r] = 0.f;
#pragma unroll
            for (int s4 = 0; s4 < 4; s4++) {
                uint32_t ap[4];
                ap[0] = f2h2(s[mi][2*s4][0],     s[mi][2*s4][1]);
                ap[1] = f2h2(s[mi][2*s4][2],     s[mi][2*s4][3]);
                ap[2] = f2h2(s[mi][2*s4 + 1][0], s[mi][2*s4 + 1][1]);
                ap[3] = f2h2(s[mi][2*s4 + 1][2], s[mi][2*s4 + 1][3]);
#pragma unroll
                for (int pn = 0; pn < 2; pn++) {
                    uint32_t t[4];
                    ldsm4(t, vt_u + (h * 32 + pn * 16 + ((lane >> 4) << 3) + (lane & 7)) * 144
                             + s4 * 32 + ((lane >> 3) & 1) * 16);
                    mma16(o[2*pn],     ap, t);
                    mma16(o[2*pn + 1], ap, t + 2);
                }
            }
            int i0 = mh * 32 + mi * 16 + g;
#pragma unroll
            for (int nd = 0; nd < 4; nd++) {
                int col = h * 32 + nd * 8 + 2 * tg;
                *(uint32_t*)(Os + i0 * 264 + col) =
                    f2h2(o[nd][0] * inv[mi][0], o[nd][1] * inv[mi][0]);
                *(uint32_t*)(Os + (i0 + 8) * 264 + col) =
                    f2h2(o[nd][2] * inv[mi][1], o[nd][3] * inv[mi][1]);
            }
        }
    }
    __syncthreads();
    // coalesced store: thread t -> row i = t>>2, 64-half segment seg = t&3
    {
        int i = tid >> 2, seg = tid & 3;
        int gpx = pxbase + ((i >> 3) << 8) + (i & 7);
        const uint4* src = (const uint4*)(Os + i * 264 + seg * 64);
        uint4* dst = (uint4*)(outA + (size_t)gpx * 256 + seg * 64);
#pragma unroll
        for (int k2 = 0; k2 < 8; k2++) dst[k2] = src[k2];
    }
}

// ---------------- 1x1 GEMM core (proj) ----------------
#define GEMM_XS_B  8192
#define GEMM_STG_B 16384
__device__ __forceinline__ void gemm_core(const __half* __restrict__ wt,
                                          const __half* __restrict__ in,
                                          uint32_t sm_u,
                                          int tid, int lane, int wm, int wn,
                                          size_t r0, int oc0, float acc[4][4][4]) {
    const int aRowB = wm * 64 + (lane & 15);
    const int bRowB = wn * 32 + ((lane >> 4) << 3) + (lane & 7);
    const uint32_t aQ = (uint32_t)(lane >> 4);
    const uint32_t bQ = (uint32_t)((lane >> 3) & 1);

    auto do_load = [&](int cc, int buf) {
        int c0 = cc * 32;
        uint32_t xs = sm_u + buf * GEMM_STG_B;
        uint32_t ws = xs + GEMM_XS_B;
#pragma unroll
        for (int jj = 0; jj < 2; jj++) {
            int j = jj * 256 + tid;
            int r = j >> 2, q = j & 3;
            cpa16(xs + r * 64 + ((q ^ ((r >> 1) & 3)) << 4),
                  in + (r0 + r) * 256 + c0 + q * 8, 16u);
        }
#pragma unroll
        for (int jj = 0; jj < 2; jj++) {
            int j = jj * 256 + tid;
            int r = j >> 2, q = j & 3;
            cpa16(ws + r * 64 + ((q ^ ((r >> 1) & 3)) << 4),
                  wt + (size_t)(oc0 + r) * 256 + c0 + q * 8, 16u);
        }
        CP_COMMIT();
    };

    auto do_compute = [&](int buf) {
        uint32_t xs = sm_u + buf * GEMM_STG_B;
        uint32_t ws = xs + GEMM_XS_B;
#pragma unroll
        for (int ks = 0; ks < 2; ks++) {
            uint32_t af[4][4];
#pragma unroll
            for (int mi = 0; mi < 4; mi++) {
                int row = aRowB + mi * 16;
                uint32_t q = (uint32_t)(ks * 2) + aQ;
                ldsm4(af[mi], xs + row * 64 + ((q ^ ((row >> 1) & 3)) << 4));
            }
            uint32_t bf[4][2];
#pragma unroll
            for (int pn = 0; pn < 2; pn++) {
                int row = bRowB + pn * 16;
                uint32_t q = (uint32_t)(ks * 2) + bQ;
                uint32_t t[4];
                ldsm4(t, ws + row * 64 + ((q ^ ((row >> 1) & 3)) << 4));
                bf[2*pn][0]   = t[0]; bf[2*pn][1]   = t[1];
                bf[2*pn+1][0] = t[2]; bf[2*pn+1][1] = t[3];
            }
#pragma unroll
            for (int mi = 0; mi < 4; mi++)
#pragma unroll
                for (int ni = 0; ni < 4; ni++)
                    mma16(acc[mi][ni], af[mi], bf[ni]);
        }
    };

    do_load(0, 0);
    do_load(1, 1);
    do_load(2, 2);
    for (int s = 0; s < 8; s++) {
        if (s < 6) { CP_WAIT2(); } else if (s == 6) { CP_WAIT1(); } else { CP_WAIT0(); }
        __syncthreads();
        if (s + 3 < 8) do_load(s + 3, (s + 3) & 3);
        do_compute(s & 3);
    }
    __syncthreads();
}

__global__ void __launch_bounds__(256, 2) gemm_proj(const __half* __restrict__ wt,
                                                    const __half* __restrict__ in,
                                                    float* __restrict__ out) {
    extern __shared__ char smc[];
    const int tid  = threadIdx.x;
    const int w    = tid >> 5, lane = tid & 31;
    const int g    = lane >> 2, tg = lane & 3;
    const int tile = blockIdx.x;
    const int oc0  = blockIdx.y << 7;
    const int b    = blockIdx.z;
    const int wm   = w >> 2, wn = w & 3;
    const uint32_t sm_u = smem_u32(smc);
    const size_t r0 = ((size_t)b << 16) + (size_t)tile * 128;

    float acc[4][4][4];
#pragma unroll
    for (int mi = 0; mi < 4; mi++)
#pragma unroll
        for (int ni = 0; ni < 4; ni++)
#pragma unroll
            for (int r = 0; r < 4; r++) acc[mi][ni][r] = 0.f;

    gemm_core(wt, in, sm_u, tid, lane, wm, wn, r0, oc0, acc);

    float* S = (float*)smc;
#pragma unroll
    for (int mi = 0; mi < 4; mi++) {
        int px = wm * 64 + mi * 16 + g;
#pragma unroll
        for (int ni = 0; ni < 4; ni++) {
            int oc = wn * 32 + ni * 8 + 2 * tg;
            S[oc * 132 + px]           = acc[mi][ni][0];
            S[(oc + 1) * 132 + px]     = acc[mi][ni][1];
            S[oc * 132 + px + 8]       = acc[mi][ni][2];
            S[(oc + 1) * 132 + px + 8] = acc[mi][ni][3];
        }
    }
    __syncthreads();
#pragma unroll
    for (int it = 0; it < 16; it++) {
        int oc = w + it * 8;
        float4 v = *(float4*)&S[oc * 132 + lane * 4];
        *(float4*)&out[(((size_t)(b * 256 + oc0 + oc)) << 16) + tile * 128 + lane * 4] = v;
    }
}

// ---------------- launch ----------------
extern "C" void kernel_launch(void* const* d_in, const int* in_sizes, int n_in,
                              void* d_out, int out_size) {
    const float* x      = (const float*)d_in[0];
    const float* w_iem  = (const float*)d_in[1];
    const float* g_iem  = (const float*)d_in[2];
    const float* b_iem  = (const float*)d_in[3];
    const float* w_nem  = (const float*)d_in[4];
    const float* g_nem  = (const float*)d_in[5];
    const float* b_nem  = (const float*)d_in[6];
    const float* w_idw  = (const float*)d_in[7];
    const float* w_ndw  = (const float*)d_in[8];
    const float* w_q    = (const float*)d_in[9];
    const float* w_k    = (const float*)d_in[10];
    const float* w_v    = (const float*)d_in[11];
    const float* w_proj = (const float*)d_in[12];
    const float* temp   = (const float*)d_in[13];
    float* out = (float*)d_out;

    float *PART, *PART2, *BNA, *BNC, *IS, *NS;
    __half *Xh, *Hc1, *Hc2, *Hd1, *Hd2, *Ha, *WCT, *WT4;
    cudaGetSymbolAddress((void**)&Xh,    g_Xh);
    cudaGetSymbolAddress((void**)&Hc1,   g_Hc1);
    cudaGetSymbolAddress((void**)&Hc2,   g_Hc2);
    cudaGetSymbolAddress((void**)&Hd1,   g_Hd1);
    cudaGetSymbolAddress((void**)&Hd2,   g_Hd2);
    cudaGetSymbolAddress((void**)&Ha,    g_Ha);
    cudaGetSymbolAddress((void**)&WCT,   g_wct);
    cudaGetSymbolAddress((void**)&WT4,   g_wt4);
    cudaGetSymbolAddress((void**)&PART,  g_part);
    cudaGetSymbolAddress((void**)&PART2, g_part2);
    cudaGetSymbolAddress((void**)&BNA,   g_bna);
    cudaGetSymbolAddress((void**)&BNC,   g_bnc);
    cudaGetSymbolAddress((void**)&IS,    g_is);
    cudaGetSymbolAddress((void**)&NS,    g_ns);

    const int CSM = CONV_STG_B * 3;               // 99840
    const int FSM = FQ_STG + 3 * FQ_SSZ;          // 169984
    const int GSM = 67584;
    cudaFuncSetAttribute(conv_mma,       cudaFuncAttributeMaxDynamicSharedMemorySize, CSM);
    cudaFuncSetAttribute(fused_qkv_attn, cudaFuncAttributeMaxDynamicSharedMemorySize, FSM);
    cudaFuncSetAttribute(gemm_proj,      cudaFuncAttributeMaxDynamicSharedMemorySize, GSM);

    tconv_kernel<<<4608, 256>>>(w_iem, w_nem, WCT);
    t1x1_kernel<<<1024, 256>>>(w_q, w_k, w_v, w_proj, WT4);
    xT_kernel<<<dim3(2048, 8, 2), dim3(32, 32)>>>(x, Xh);

    conv_mma<<<dim3(512, 2, 4), 256, CSM>>>(Xh, WCT, Hc1, Hc2, PART);

    bnstats2a<<<dim3(2, 32), 256>>>(PART, PART2);
    bnstats2b<<<2, 256>>>(PART2, g_iem, b_iem, g_nem, b_nem, BNA, BNC);

    dwconv_t<<<dim3(65536, 2), 128>>>(Hc1, Hc2, BNA, BNC, w_idw, w_ndw,
                                      Hd1, Hd2, IS, NS);

    fused_qkv_attn<<<dim3(1024, 2), 256, FSM>>>(WT4, Hd1, Hd2, Xh, IS, NS, temp, Ha);

    gemm_proj<<<dim3(512, 2, 2), 256, GSM>>>(WT4 + 3 * 65536, Ha, out);
}

// round 16
// speedup vs baseline: 1.1162x; 1.1162x over previous
#include <cuda_runtime.h>
#include <cuda_fp16.h>
#include <math.h>
#include <stdint.h>

#define HW 65536
#define NBUF (2*256*HW)

// ---------------- static scratch (all big intermediates fp16) ----------------
__device__ __half g_Xh[NBUF];       // x [b][px][c]
__device__ __half g_Hc1[NBUF];      // conv_iem out [r][c]
__device__ __half g_Hc2[NBUF];      // conv_nem out [r][c]
__device__ __half g_Hd1[NBUF];      // illum map [r][c]
__device__ __half g_Hd2[NBUF];      // noise map [r][c]
__device__ __half g_Hq[NBUF];       // q [r][c]
__device__ __half g_Hk[NBUF];       // k [r][c]
__device__ __half g_Hv[NBUF];       // v [r][c]
__device__ __half g_Ha[NBUF];       // attn out [r][c]
__device__ __half g_wct[2*589824];  // conv weights [m][tap][oc][c]
__device__ __half g_wt4[4*65536];   // 1x1 weights [m][oc][c]
__device__ float  g_part[1048576];  // bn partials [2][1024 cta][2][256 ch]
__device__ float  g_part2[32768];   // bn partials lvl2 [2][32][2][256]
__device__ float  g_bna[512];
__device__ float  g_bnc[512];
__device__ float  g_is[2*HW];
__device__ float  g_ns[2*HW];

// ---------------- helpers ----------------
__device__ __forceinline__ uint32_t smem_u32(const void* p) {
    uint32_t a;
    asm("{ .reg .u64 t; cvta.to.shared.u64 t, %1; cvt.u32.u64 %0, t; }" : "=r"(a) : "l"(p));
    return a;
}
__device__ __forceinline__ uint32_t f2h2(float a, float b) {
    __half2 h = __floats2half2_rn(a, b);
    return *(uint32_t*)&h;
}
__device__ __forceinline__ void h8_to_f(uint4 t, float* f) {
    const __half2* hp = (const __half2*)&t;
#pragma unroll
    for (int u = 0; u < 4; u++) {
        float2 ff = __half22float2(hp[u]);
        f[2*u] = ff.x; f[2*u+1] = ff.y;
    }
}
__device__ __forceinline__ void cpa16(uint32_t s, const void* g, uint32_t n) {
    asm volatile("cp.async.cg.shared.global [%0], [%1], 16, %2;"
                 :: "r"(s), "l"(g), "r"(n) : "memory");
}
#define CP_COMMIT()  asm volatile("cp.async.commit_group;" ::: "memory")
#define CP_WAIT2()   asm volatile("cp.async.wait_group 2;" ::: "memory")
#define CP_WAIT1()   asm volatile("cp.async.wait_group 1;" ::: "memory")
#define CP_WAIT0()   asm volatile("cp.async.wait_group 0;" ::: "memory")

// fp16 m16n8k16 mma, fp32 accumulate (family-portable HMMA)
__device__ __forceinline__ void mma16(float* d, const uint32_t* a, const uint32_t* b) {
    asm volatile("mma.sync.aligned.m16n8k16.row.col.f32.f16.f16.f32 "
        "{%0,%1,%2,%3}, {%4,%5,%6,%7}, {%8,%9}, {%0,%1,%2,%3};"
        : "+f"(d[0]), "+f"(d[1]), "+f"(d[2]), "+f"(d[3])
        : "r"(a[0]), "r"(a[1]), "r"(a[2]), "r"(a[3]), "r"(b[0]), "r"(b[1]));
}
// ldmatrix x4 (sm_75+, family-portable)
__device__ __forceinline__ void ldsm4(uint32_t* r, uint32_t a) {
    asm volatile("ldmatrix.sync.aligned.m8n8.x4.shared.b16 {%0,%1,%2,%3}, [%4];"
        : "=r"(r[0]), "=r"(r[1]), "=r"(r[2]), "=r"(r[3]) : "r"(a));
}

// ---------------- merged weight prep (conv blocks 0..4607, 1x1 blocks 4608..5631) ----------------
__global__ void wprep_kernel(const float* __restrict__ w0, const float* __restrict__ w1,
                             const float* __restrict__ wq, const float* __restrict__ wk,
                             const float* __restrict__ wv, const float* __restrict__ wp,
                             __half* __restrict__ outc, __half* __restrict__ out1) {
    if (blockIdx.x < 4608) {
        int i = blockIdx.x * 256 + threadIdx.x;          // 2*589824
        int m = i / 589824;
        int r = i - m * 589824;
        int tap = r >> 16;
        int rem = r & 65535;
        int oc  = rem >> 8;
        int c   = rem & 255;
        const float* w = m ? w1 : w0;
        outc[i] = __float2half_rn(w[oc * 2304 + c * 9 + tap]);
    } else {
        int i = (blockIdx.x - 4608) * 256 + threadIdx.x; // 4*65536
        int m = i >> 16;
        int r = i & 65535;
        int o = r >> 8;
        int c = r & 255;
        const float* w = (m == 0) ? wq : (m == 1) ? wk : (m == 2) ? wv : wp;
        out1[i] = __float2half_rn(w[o * 256 + c]);
    }
}

// ---------------- x transpose: NCHW -> [b][px][c] fp16 (half2 stores) ----------------
__global__ void xT_kernel(const float* __restrict__ x, __half* __restrict__ xT) {
    __shared__ float t[32][33];
    int b  = blockIdx.z;
    int c0 = blockIdx.y * 32;
    int p0 = blockIdx.x * 32;
    int tx = threadIdx.x, ty = threadIdx.y;
    t[ty][tx] = x[(((size_t)((b << 8) + c0 + ty)) << 16) + p0 + tx];
    __syncthreads();
    int u = ty * 32 + tx;
    if (u < 512) {
        int r = u >> 4, cp = u & 15;
        __half2 hv = __floats2half2_rn(t[2*cp][r], t[2*cp + 1][r]);
        *(__half2*)(xT + (((size_t)((b << 16) + p0 + r)) << 8) + c0 + 2 * cp) = hv;
    }
}

// ---------------- 3x3 conv implicit GEMM (fp16 mma + ldmatrix), 3-stage,
//                  both convs in one launch, BN partials fused ----------------
#define CONV_XS_B  8704
#define CONV_STG_B 33280
__global__ void __launch_bounds__(256, 2) conv_mma(const __half* __restrict__ xT,
                                                   const __half* __restrict__ W2base,
                                                   __half* __restrict__ out1,
                                                   __half* __restrict__ out2,
                                                   float* __restrict__ part) {
    extern __shared__ char smc[];
    const int tid  = threadIdx.x;
    const int w    = tid >> 5, lane = tid & 31;
    const int g    = lane >> 2, tg = lane & 3;
    const int y    = blockIdx.x >> 1;
    const int p0   = (blockIdx.x & 1) << 7;
    const int oc0  = blockIdx.y << 7;
    const int m    = blockIdx.z >> 1;
    const int b    = blockIdx.z & 1;
    const __half* W2 = W2base + (size_t)m * 589824;
    __half* out = m ? out2 : out1;
    const int wm   = w >> 2, wn = w & 3;
    const uint32_t sm_u = smem_u32(smc);
    const int aRowB = wm * 64 + (lane & 15);
    const int bRowB = wn * 32 + ((lane >> 4) << 3) + (lane & 7);
    const uint32_t aQ = (uint32_t)(lane >> 4);
    const uint32_t bQ = (uint32_t)((lane >> 3) & 1);

    float acc[4][4][4];
#pragma unroll
    for (int mi = 0; mi < 4; mi++)
#pragma unroll
        for (int ni = 0; ni < 4; ni++)
#pragma unroll
            for (int r = 0; r < 4; r++) acc[mi][ni][r] = 0.f;

    auto do_load = [&](int step, int buf) {
        int cc = step / 3;
        int ky = step - cc * 3;
        int c0 = cc * 32;
        uint32_t xs = sm_u + buf * CONV_STG_B;
        uint32_t ws = xs + CONV_XS_B;
        int yin = y + ky - 1;
        bool yok = (unsigned)yin < 256u;
#pragma unroll
        for (int jj = 0; jj < 3; jj++) {
            int j = jj * 256 + tid;
            if (j < 520) {
                int r = j >> 2, q = j & 3;
                int xin = p0 + r - 1;
                bool ok = yok && ((unsigned)xin < 256u);
                const __half* src = ok
                    ? xT + ((((size_t)b << 16) + ((size_t)yin << 8) + xin) << 8) + c0 + q * 8
                    : xT;
                cpa16(xs + r * 64 + ((q ^ ((r >> 1) & 3)) << 4), src, ok ? 16u : 0u);
            }
        }
#pragma unroll
        for (int jj = 0; jj < 6; jj++) {
            int j = jj * 256 + tid;
            int row = j >> 2, q = j & 3;          // row = kx*128+oc
            int kx = row >> 7, oc = row & 127;
            int tap = ky * 3 + kx;
            cpa16(ws + row * 64 + ((q ^ ((row >> 1) & 3)) << 4),
                  W2 + (((size_t)(tap * 256 + oc0 + oc)) << 8) + c0 + q * 8, 16u);
        }
        CP_COMMIT();
    };

    auto do_compute = [&](int buf) {
        uint32_t xs = sm_u + buf * CONV_STG_B;
        uint32_t ws = xs + CONV_XS_B;
#pragma unroll
        for (int kx = 0; kx < 3; kx++) {
#pragma unroll
            for (int ks = 0; ks < 2; ks++) {
                uint32_t af[4][4];
#pragma unroll
                for (int mi = 0; mi < 4; mi++) {
                    int row = aRowB + mi * 16 + kx;
                    uint32_t q = (uint32_t)(ks * 2) + aQ;
                    ldsm4(af[mi], xs + row * 64 + ((q ^ ((row >> 1) & 3)) << 4));
                }
                uint32_t bf[4][2];
#pragma unroll
                for (int pn = 0; pn < 2; pn++) {
                    int row = kx * 128 + bRowB + pn * 16;
                    uint32_t q = (uint32_t)(ks * 2) + bQ;
                    uint32_t t[4];
                    ldsm4(t, ws + row * 64 + ((q ^ ((row >> 1) & 3)) << 4));
                    bf[2*pn][0]   = t[0]; bf[2*pn][1]   = t[1];
                    bf[2*pn+1][0] = t[2]; bf[2*pn+1][1] = t[3];
                }
#pragma unroll
                for (int mi = 0; mi < 4; mi++)
#pragma unroll
                    for (int ni = 0; ni < 4; ni++)
                        mma16(acc[mi][ni], af[mi], bf[ni]);
            }
        }
    };

    do_load(0, 0);
    do_load(1, 1);
    for (int s = 0; s < 24; s++) {
        if (s < 23) { CP_WAIT1(); } else { CP_WAIT0(); }
        __syncthreads();
        if (s + 2 < 24) do_load(s + 2, (s + 2) % 3);
        do_compute(s % 3);
    }
    __syncthreads();

    float* S = (float*)smc;     // 128*132*4 = 67584
#pragma unroll
    for (int mi = 0; mi < 4; mi++) {
        int px = wm * 64 + mi * 16 + g;
#pragma unroll
        for (int ni = 0; ni < 4; ni++) {
            int oc = wn * 32 + ni * 8 + 2 * tg;
            S[px * 132 + oc]           = acc[mi][ni][0];
            S[px * 132 + oc + 1]       = acc[mi][ni][1];
            S[(px + 8) * 132 + oc]     = acc[mi][ni][2];
            S[(px + 8) * 132 + oc + 1] = acc[mi][ni][3];
        }
    }
    __syncthreads();
#pragma unroll
    for (int it = 0; it < 16; it++) {
        int px = w + it * 8;
        float4 v = *(float4*)&S[px * 132 + lane * 4];
        uint2 o;
        o.x = f2h2(v.x, v.y);
        o.y = f2h2(v.z, v.w);
        *(uint2*)(out + (((size_t)((b << 16) + (y << 8) + p0 + px)) << 8) + oc0 + lane * 4) = o;
    }
    // fused BN partials
    float* R = (float*)(smc + 67584);
    {
        int ocl = tid & 127, half = tid >> 7;
        float s = 0.f, s2 = 0.f;
#pragma unroll 8
        for (int px = 0; px < 64; px++) {
            float v = S[(half * 64 + px) * 132 + ocl];
            s += v; s2 = fmaf(v, v, s2);
        }
        R[(half * 128 + ocl) * 2]     = s;
        R[(half * 128 + ocl) * 2 + 1] = s2;
    }
    __syncthreads();
    if (tid < 128) {
        float s  = R[tid * 2]     + R[(128 + tid) * 2];
        float s2 = R[tid * 2 + 1] + R[(128 + tid) * 2 + 1];
        size_t base = ((size_t)(m * 1024 + b * 512 + blockIdx.x) * 2) * 256 + oc0 + tid;
        part[base]       = s;
        part[base + 256] = s2;
    }
}

// ---------------- BN stats: two-stage parallel reduce ----------------
__global__ void bnstats2a(const float* __restrict__ part, float* __restrict__ part2) {
    int m = blockIdx.x, chunk = blockIdx.y;
    int c = threadIdx.x;
    float s = 0.f, s2 = 0.f;
    for (int r = 0; r < 32; r++) {
        size_t base = ((size_t)(m * 1024 + chunk * 32 + r) * 2) * 256;
        s  += part[base + c];
        s2 += part[base + 256 + c];
    }
    size_t ob = ((size_t)(m * 32 + chunk) * 2) * 256;
    part2[ob + c]       = s;
    part2[ob + 256 + c] = s2;
}

__global__ void bnstats2b(const float* __restrict__ part2,
                          const float* __restrict__ g1, const float* __restrict__ b1,
                          const float* __restrict__ g2, const float* __restrict__ b2,
                          float* __restrict__ pa, float* __restrict__ pc) {
    int m = blockIdx.x;
    const float* gamma = m ? g2 : g1;
    const float* beta  = m ? b2 : b1;
    int c = threadIdx.x;
    float s = 0.f, s2 = 0.f;
    for (int r = 0; r < 32; r++) {
        size_t base = ((size_t)(m * 32 + r) * 2) * 256;
        s  += part2[base + c];
        s2 += part2[base + 256 + c];
    }
    float mean = s  * (1.f / 131072.f);
    float var  = s2 * (1.f / 131072.f) - mean * mean;
    float a = gamma[c] * rsqrtf(var + 1e-5f);
    pa[m * 256 + c] = a;
    pc[m * 256 + c] = beta[c] - mean * a;
}

// ---------------- depthwise conv pair, half2 loads, 2ch x 2px per thread,
//                  BN+relu6 fused, channel-mean fused ----------------
__global__ void __launch_bounds__(128) dwconv_t(
                         const __half* __restrict__ in1, const __half* __restrict__ in2,
                         const float* __restrict__ pa, const float* __restrict__ pc,
                         const float* __restrict__ wd1, const float* __restrict__ wd2,
                         __half* __restrict__ out1, __half* __restrict__ out2,
                         float* __restrict__ mean1, float* __restrict__ mean2) {
    __shared__ float red0[4], red1[4];
    int m = blockIdx.y;
    const __half* in  = m ? in2 : in1;
    const float*  wdw = m ? wd2 : wd1;
    __half* out       = m ? out2 : out1;
    float* mean_out   = m ? mean2 : mean1;
    int j = blockIdx.x;          // rows 2j, 2j+1 (same image row)
    int c2 = threadIdx.x;        // channel pair 0..127
    int r0 = j << 1;
    int p  = r0 & 65535;
    int y = p >> 8, xx = p & 255;          // xx even
    size_t bb = (size_t)(r0 - p) << 8;
    float a0 = pa[m * 256 + 2 * c2],     cb0 = pc[m * 256 + 2 * c2];
    float a1 = pa[m * 256 + 2 * c2 + 1], cb1 = pc[m * 256 + 2 * c2 + 1];
    float w0[9], w1[9];
#pragma unroll
    for (int t = 0; t < 9; t++) {
        w0[t] = wdw[(2 * c2) * 9 + t];
        w1[t] = wdw[(2 * c2 + 1) * 9 + t];
    }
    float accA0 = 0.f, accA1 = 0.f, accB0 = 0.f, accB1 = 0.f;
#pragma unroll
    for (int ky = 0; ky < 3; ky++) {
        int yy = y + ky - 1;
        if ((unsigned)yy >= 256u) continue;
        float v0[4], v1[4];
#pragma unroll
        for (int dx = 0; dx < 4; dx++) {
            int xv = xx + dx - 1;
            bool ok = (unsigned)xv < 256u;
            float2 f = {0.f, 0.f};
            if (ok) {
                __half2 hv = *(const __half2*)(in + (bb + (size_t)((yy << 8) + xv) * 256) + 2 * c2);
                f = __half22float2(hv);
            }
            float t0 = fminf(fmaxf(f.x * a0 + cb0, 0.f), 6.f);
            float t1 = fminf(fmaxf(f.y * a1 + cb1, 0.f), 6.f);
            v0[dx] = ok ? t0 : 0.f;
            v1[dx] = ok ? t1 : 0.f;
        }
        accA0 = fmaf(w0[ky*3+0], v0[0], accA0); accA0 = fmaf(w0[ky*3+1], v0[1], accA0); accA0 = fmaf(w0[ky*3+2], v0[2], accA0);
        accA1 = fmaf(w1[ky*3+0], v1[0], accA1); accA1 = fmaf(w1[ky*3+1], v1[1], accA1); accA1 = fmaf(w1[ky*3+2], v1[2], accA1);
        accB0 = fmaf(w0[ky*3+0], v0[1], accB0); accB0 = fmaf(w0[ky*3+1], v0[2], accB0); accB0 = fmaf(w0[ky*3+2], v0[3], accB0);
        accB1 = fmaf(w1[ky*3+0], v1[1], accB1); accB1 = fmaf(w1[ky*3+1], v1[2], accB1); accB1 = fmaf(w1[ky*3+2], v1[3], accB1);
    }
    *(__half2*)(out + (size_t)r0 * 256 + 2 * c2)       = __floats2half2_rn(accA0, accA1);
    *(__half2*)(out + (size_t)(r0 + 1) * 256 + 2 * c2) = __floats2half2_rn(accB0, accB1);

    float s0 = accA0 + accA1, s1 = accB0 + accB1;
#pragma unroll
    for (int off = 16; off; off >>= 1) {
        s0 += __shfl_xor_sync(0xffffffffu, s0, off);
        s1 += __shfl_xor_sync(0xffffffffu, s1, off);
    }
    if ((c2 & 31) == 0) { red0[c2 >> 5] = s0; red1[c2 >> 5] = s1; }
    __syncthreads();
    if (c2 < 4) {
        float t0 = red0[c2], t1 = red1[c2];
#pragma unroll
        for (int off = 2; off; off >>= 1) {
            t0 += __shfl_xor_sync(0xfu, t0, off);
            t1 += __shfl_xor_sync(0xfu, t1, off);
        }
        if (c2 == 0) {
            mean_out[r0]     = t0 * (1.f / 256.f);
            mean_out[r0 + 1] = t1 * (1.f / 256.f);
        }
    }
}

// ---------------- 1x1 GEMM core (fp16 mma + ldmatrix), 4-stage/3-deep ----------------
#define GEMM_XS_B  8192
#define GEMM_STG_B 16384
__device__ __forceinline__ void gemm_core(const __half* __restrict__ wt,
                                          const __half* __restrict__ in,
                                          uint32_t sm_u,
                                          int tid, int lane, int wm, int wn,
                                          size_t r0, int oc0, float acc[4][4][4]) {
    const int aRowB = wm * 64 + (lane & 15);
    const int bRowB = wn * 32 + ((lane >> 4) << 3) + (lane & 7);
    const uint32_t aQ = (uint32_t)(lane >> 4);
    const uint32_t bQ = (uint32_t)((lane >> 3) & 1);

    auto do_load = [&](int cc, int buf) {
        int c0 = cc * 32;
        uint32_t xs = sm_u + buf * GEMM_STG_B;
        uint32_t ws = xs + GEMM_XS_B;
#pragma unroll
        for (int jj = 0; jj < 2; jj++) {
            int j = jj * 256 + tid;
            int r = j >> 2, q = j & 3;
            cpa16(xs + r * 64 + ((q ^ ((r >> 1) & 3)) << 4),
                  in + (r0 + r) * 256 + c0 + q * 8, 16u);
        }
#pragma unroll
        for (int jj = 0; jj < 2; jj++) {
            int j = jj * 256 + tid;
            int r = j >> 2, q = j & 3;
            cpa16(ws + r * 64 + ((q ^ ((r >> 1) & 3)) << 4),
                  wt + (size_t)(oc0 + r) * 256 + c0 + q * 8, 16u);
        }
        CP_COMMIT();
    };

    auto do_compute = [&](int buf) {
        uint32_t xs = sm_u + buf * GEMM_STG_B;
        uint32_t ws = xs + GEMM_XS_B;
#pragma unroll
        for (int ks = 0; ks < 2; ks++) {
            uint32_t af[4][4];
#pragma unroll
            for (int mi = 0; mi < 4; mi++) {
                int row = aRowB + mi * 16;
                uint32_t q = (uint32_t)(ks * 2) + aQ;
                ldsm4(af[mi], xs + row * 64 + ((q ^ ((row >> 1) & 3)) << 4));
            }
            uint32_t bf[4][2];
#pragma unroll
            for (int pn = 0; pn < 2; pn++) {
                int row = bRowB + pn * 16;
                uint32_t q = (uint32_t)(ks * 2) + bQ;
                uint32_t t[4];
                ldsm4(t, ws + row * 64 + ((q ^ ((row >> 1) & 3)) << 4));
                bf[2*pn][0]   = t[0]; bf[2*pn][1]   = t[1];
                bf[2*pn+1][0] = t[2]; bf[2*pn+1][1] = t[3];
            }
#pragma unroll
            for (int mi = 0; mi < 4; mi++)
#pragma unroll
                for (int ni = 0; ni < 4; ni++)
                    mma16(acc[mi][ni], af[mi], bf[ni]);
        }
    };

    do_load(0, 0);
    do_load(1, 1);
    do_load(2, 2);
    for (int s = 0; s < 8; s++) {
        if (s < 6) { CP_WAIT2(); } else if (s == 6) { CP_WAIT1(); } else { CP_WAIT0(); }
        __syncthreads();
        if (s + 3 < 8) do_load(s + 3, (s + 3) & 3);
        do_compute(s & 3);
    }
    __syncthreads();
}

// q/k/v in one launch: grid (512, 2, 6); outputs plain [r][c] fp16
__global__ void __launch_bounds__(256, 2) gemm_qkv(const __half* __restrict__ wtb,
                                                   const __half* __restrict__ in1,
                                                   const __half* __restrict__ in2,
                                                   const __half* __restrict__ in3,
                                                   __half* __restrict__ o1,
                                                   __half* __restrict__ o2,
                                                   __half* __restrict__ o3) {
    extern __shared__ char smc[];
    const int tid  = threadIdx.x;
    const int w    = tid >> 5, lane = tid & 31;
    const int g    = lane >> 2, tg = lane & 3;
    const int tile = blockIdx.x;
    const int oc0  = blockIdx.y << 7;
    const int which = blockIdx.z >> 1;
    const int b    = blockIdx.z & 1;
    const int wm   = w >> 2, wn = w & 3;
    const __half* wt = wtb + (size_t)which * 65536;
    const __half* in = (which == 0) ? in1 : (which == 1) ? in2 : in3;
    __half* out      = (which == 0) ? o1  : (which == 1) ? o2  : o3;
    const uint32_t sm_u = smem_u32(smc);
    const size_t r0 = ((size_t)b << 16) + (size_t)tile * 128;

    float acc[4][4][4];
#pragma unroll
    for (int mi = 0; mi < 4; mi++)
#pragma unroll
        for (int ni = 0; ni < 4; ni++)
#pragma unroll
            for (int r = 0; r < 4; r++) acc[mi][ni][r] = 0.f;

    gemm_core(wt, in, sm_u, tid, lane, wm, wn, r0, oc0, acc);

    float* S = (float*)smc;
#pragma unroll
    for (int mi = 0; mi < 4; mi++) {
        int px = wm * 64 + mi * 16 + g;
#pragma unroll
        for (int ni = 0; ni < 4; ni++) {
            int oc = wn * 32 + ni * 8 + 2 * tg;
            S[px * 132 + oc]           = acc[mi][ni][0];
            S[px * 132 + oc + 1]       = acc[mi][ni][1];
            S[(px + 8) * 132 + oc]     = acc[mi][ni][2];
            S[(px + 8) * 132 + oc + 1] = acc[mi][ni][3];
        }
    }
    __syncthreads();
#pragma unroll
    for (int it = 0; it < 16; it++) {
        int px = w + it * 8;
        float4 v = *(float4*)&S[px * 132 + lane * 4];
        uint2 o;
        o.x = f2h2(v.x, v.y);
        o.y = f2h2(v.z, v.w);
        *(uint2*)(out + ((r0 + px) << 8) + oc0 + lane * 4) = o;
    }
}

// proj: NCHW fp32 out
__global__ void __launch_bounds__(256, 2) gemm_proj(const __half* __restrict__ wt,
                                                    const __half* __restrict__ in,
                                                    float* __restrict__ out) {
    extern __shared__ char smc[];
    const int tid  = threadIdx.x;
    const int w    = tid >> 5, lane = tid & 31;
    const int g    = lane >> 2, tg = lane & 3;
    const int tile = blockIdx.x;
    const int oc0  = blockIdx.y << 7;
    const int b    = blockIdx.z;
    const int wm   = w >> 2, wn = w & 3;
    const uint32_t sm_u = smem_u32(smc);
    const size_t r0 = ((size_t)b << 16) + (size_t)tile * 128;

    float acc[4][4][4];
#pragma unroll
    for (int mi = 0; mi < 4; mi++)
#pragma unroll
        for (int ni = 0; ni < 4; ni++)
#pragma unroll
            for (int r = 0; r < 4; r++) acc[mi][ni][r] = 0.f;

    gemm_core(wt, in, sm_u, tid, lane, wm, wn, r0, oc0, acc);

    float* S = (float*)smc;
#pragma unroll
    for (int mi = 0; mi < 4; mi++) {
        int px = wm * 64 + mi * 16 + g;
#pragma unroll
        for (int ni = 0; ni < 4; ni++) {
            int oc = wn * 32 + ni * 8 + 2 * tg;
            S[oc * 132 + px]           = acc[mi][ni][0];
            S[(oc + 1) * 132 + px]     = acc[mi][ni][1];
            S[oc * 132 + px + 8]       = acc[mi][ni][2];
            S[(oc + 1) * 132 + px + 8] = acc[mi][ni][3];
        }
    }
    __syncthreads();
#pragma unroll
    for (int it = 0; it < 16; it++) {
        int oc = w + it * 8;
        float4 v = *(float4*)&S[oc * 132 + lane * 4];
        *(float4*)&out[(((size_t)(b * 256 + oc0 + oc)) << 16) + tile * 128 + lane * 4] = v;
    }
}

// ---------------- windowed attention on tensor cores ----------------
// 1 block = 1 window, 128 threads = 4 warps (warp w owns q-rows 16w..16w+15).
__global__ void __launch_bounds__(128) attn_mma(const __half* __restrict__ q,
                                                const __half* __restrict__ k,
                                                const __half* __restrict__ v,
                                                const float* __restrict__ is,
                                                const float* __restrict__ ns,
                                                const float* __restrict__ temp,
                                                __half* __restrict__ out) {
    __shared__ __align__(16) __half Qs[64 * 40];   // 80B rows
    __shared__ __align__(16) __half Ks[64 * 40];
    __shared__ __align__(16) __half Vt[32 * 72];   // 144B rows, [d][j]
    const int t   = threadIdx.x;
    const int win = blockIdx.x;
    const int h   = blockIdx.y;
    const int b   = blockIdx.z;
    const int w   = t >> 5, lane = t & 31;
    const int g   = lane >> 2, tg = lane & 3;

    // ---- load + scale phase: 2 threads per row ----
    {
        int i = t >> 1, hp = t & 1;
        int y = ((win >> 5) << 3) + (i >> 3);
        int x = ((win & 31) << 3) + (i & 7);
        int pidx = (b << 16) + (y << 8) + x;
        size_t rc = ((size_t)pidx << 8) + (h << 5) + hp * 16;
        float qf[16], kf[16], vf[16];
        {
            const uint4* p4 = (const uint4*)(q + rc);
            h8_to_f(p4[0], qf); h8_to_f(p4[1], qf + 8);
        }
        {
            const uint4* p4 = (const uint4*)(k + rc);
            h8_to_f(p4[0], kf); h8_to_f(p4[1], kf + 8);
        }
        {
            const uint4* p4 = (const uint4*)(v + rc);
            h8_to_f(p4[0], vf); h8_to_f(p4[1], vf + 8);
        }
        float qn = 0.f, kn = 0.f;
#pragma unroll
        for (int u = 0; u < 16; u++) {
            qn = fmaf(qf[u], qf[u], qn);
            kn = fmaf(kf[u], kf[u], kn);
        }
        qn += __shfl_xor_sync(0xffffffffu, qn, 1);
        kn += __shfl_xor_sync(0xffffffffu, kn, 1);
        float nsv = ns[pidx];
        float kmul = fminf(fmaxf(1.f - nsv, 0.f), 1.f) / fmaxf(sqrtf(kn), 1e-12f);
        float qmul = (1.f + is[pidx]) / fmaxf(sqrtf(qn), 1e-12f)
                   * 0.17677669529663687f * temp[h];
        __half2* qrow = (__half2*)(Qs + i * 40 + hp * 16);
        __half2* krow = (__half2*)(Ks + i * 40 + hp * 16);
#pragma unroll
        for (int u = 0; u < 8; u++) {
            qrow[u] = __floats2half2_rn(qf[2*u] * qmul, qf[2*u+1] * qmul);
            krow[u] = __floats2half2_rn(kf[2*u] * kmul, kf[2*u+1] * kmul);
        }
#pragma unroll
        for (int u = 0; u < 16; u++)
            Vt[(hp * 16 + u) * 72 + i] = __float2half_rn(vf[u]);
    }
    __syncthreads();

    const uint32_t qs_u = smem_u32(Qs);
    const uint32_t ks_u = smem_u32(Ks);
    const uint32_t vt_u = smem_u32(Vt);

    // ---- QK^T: M=64 N=64 K=32 ----
    float s[8][4];
#pragma unroll
    for (int ni = 0; ni < 8; ni++)
#pragma unroll
        for (int r = 0; r < 4; r++) s[ni][r] = 0.f;
#pragma unroll
    for (int ks = 0; ks < 2; ks++) {
        uint32_t af[4];
        ldsm4(af, qs_u + (16 * w + (lane & 15)) * 80 + ks * 32 + (lane >> 4) * 16);
#pragma unroll
        for (int pn = 0; pn < 4; pn++) {
            uint32_t tt[4];
            ldsm4(tt, ks_u + (pn * 16 + ((lane >> 4) << 3) + (lane & 7)) * 80
                       + ks * 32 + ((lane >> 3) & 1) * 16);
            mma16(s[2*pn],     af, tt);
            mma16(s[2*pn + 1], af, tt + 2);
        }
    }

    // ---- softmax in fragments (rows g, g+8 of warp block) ----
    float mx0 = -1e30f, mx1 = -1e30f;
#pragma unroll
    for (int ni = 0; ni < 8; ni++) {
        mx0 = fmaxf(mx0, fmaxf(s[ni][0], s[ni][1]));
        mx1 = fmaxf(mx1, fmaxf(s[ni][2], s[ni][3]));
    }
    mx0 = fmaxf(mx0, __shfl_xor_sync(0xffffffffu, mx0, 1));
    mx0 = fmaxf(mx0, __shfl_xor_sync(0xffffffffu, mx0, 2));
    mx1 = fmaxf(mx1, __shfl_xor_sync(0xffffffffu, mx1, 1));
    mx1 = fmaxf(mx1, __shfl_xor_sync(0xffffffffu, mx1, 2));
    float sum0 = 0.f, sum1 = 0.f;
#pragma unroll
    for (int ni = 0; ni < 8; ni++) {
        s[ni][0] = __expf(s[ni][0] - mx0);
        s[ni][1] = __expf(s[ni][1] - mx0);
        s[ni][2] = __expf(s[ni][2] - mx1);
        s[ni][3] = __expf(s[ni][3] - mx1);
        sum0 += s[ni][0] + s[ni][1];
        sum1 += s[ni][2] + s[ni][3];
    }
    sum0 += __shfl_xor_sync(0xffffffffu, sum0, 1);
    sum0 += __shfl_xor_sync(0xffffffffu, sum0, 2);
    sum1 += __shfl_xor_sync(0xffffffffu, sum1, 1);
    sum1 += __shfl_xor_sync(0xffffffffu, sum1, 2);
    float inv0 = 1.f / sum0, inv1 = 1.f / sum1;

    // ---- P x V: M=64 N=32 K=64 (P repacked c-frag -> a-frag) ----
    float o[4][4];
#pragma unroll
    for (int nd = 0; nd < 4; nd++)
#pragma unroll
        for (int r = 0; r < 4; r++) o[nd][r] = 0.f;
#pragma unroll
    for (int s4 = 0; s4 < 4; s4++) {
        uint32_t ap[4];
        ap[0] = f2h2(s[2*s4][0],     s[2*s4][1]);
        ap[1] = f2h2(s[2*s4][2],     s[2*s4][3]);
        ap[2] = f2h2(s[2*s4 + 1][0], s[2*s4 + 1][1]);
        ap[3] = f2h2(s[2*s4 + 1][2], s[2*s4 + 1][3]);
        uint32_t tt[4];
        ldsm4(tt, vt_u + (((lane >> 4) << 3) + (lane & 7)) * 144
                   + s4 * 32 + ((lane >> 3) & 1) * 16);
        mma16(o[0], ap, tt);
        mma16(o[1], ap, tt + 2);
        ldsm4(tt, vt_u + (16 + ((lane >> 4) << 3) + (lane & 7)) * 144
                   + s4 * 32 + ((lane >> 3) & 1) * 16);
        mma16(o[2], ap, tt);
        mma16(o[3], ap, tt + 2);
    }

    // ---- stage output in smem (reuse Qs: own rows only), coalesced store ----
    __half2* Os = (__half2*)Qs;
#pragma unroll
    for (int nd = 0; nd < 4; nd++) {
        int col2 = (nd * 8 + 2 * tg) >> 1;
        Os[(16 * w + g)     * 20 + col2] = __floats2half2_rn(o[nd][0] * inv0, o[nd][1] * inv0);
        Os[(16 * w + g + 8) * 20 + col2] = __floats2half2_rn(o[nd][2] * inv1, o[nd][3] * inv1);
    }
    __syncthreads();
    {
        int i = t >> 1, hp = t & 1;
        int y = ((win >> 5) << 3) + (i >> 3);
        int x = ((win & 31) << 3) + (i & 7);
        int pidx = (b << 16) + (y << 8) + x;
        size_t rc = ((size_t)pidx << 8) + (h << 5) + hp * 16;
        const uint4* src = (const uint4*)(Qs + i * 40 + hp * 16);
        uint4* dst = (uint4*)(out + rc);
        dst[0] = src[0];
        dst[1] = src[1];
    }
}

// ---------------- launch ----------------
extern "C" void kernel_launch(void* const* d_in, const int* in_sizes, int n_in,
                              void* d_out, int out_size) {
    const float* x      = (const float*)d_in[0];
    const float* w_iem  = (const float*)d_in[1];
    const float* g_iem  = (const float*)d_in[2];
    const float* b_iem  = (const float*)d_in[3];
    const float* w_nem  = (const float*)d_in[4];
    const float* g_nem  = (const float*)d_in[5];
    const float* b_nem  = (const float*)d_in[6];
    const float* w_idw  = (const float*)d_in[7];
    const float* w_ndw  = (const float*)d_in[8];
    const float* w_q    = (const float*)d_in[9];
    const float* w_k    = (const float*)d_in[10];
    const float* w_v    = (const float*)d_in[11];
    const float* w_proj = (const float*)d_in[12];
    const float* temp   = (const float*)d_in[13];
    float* out = (float*)d_out;

    float *PART, *PART2, *BNA, *BNC, *IS, *NS;
    __half *Xh, *Hc1, *Hc2, *Hd1, *Hd2, *Hq, *Hk, *Hv, *Ha, *WCT, *WT4;
    cudaGetSymbolAddress((void**)&Xh,    g_Xh);
    cudaGetSymbolAddress((void**)&Hc1,   g_Hc1);
    cudaGetSymbolAddress((void**)&Hc2,   g_Hc2);
    cudaGetSymbolAddress((void**)&Hd1,   g_Hd1);
    cudaGetSymbolAddress((void**)&Hd2,   g_Hd2);
    cudaGetSymbolAddress((void**)&Hq,    g_Hq);
    cudaGetSymbolAddress((void**)&Hk,    g_Hk);
    cudaGetSymbolAddress((void**)&Hv,    g_Hv);
    cudaGetSymbolAddress((void**)&Ha,    g_Ha);
    cudaGetSymbolAddress((void**)&WCT,   g_wct);
    cudaGetSymbolAddress((void**)&WT4,   g_wt4);
    cudaGetSymbolAddress((void**)&PART,  g_part);
    cudaGetSymbolAddress((void**)&PART2, g_part2);
    cudaGetSymbolAddress((void**)&BNA,   g_bna);
    cudaGetSymbolAddress((void**)&BNC,   g_bnc);
    cudaGetSymbolAddress((void**)&IS,    g_is);
    cudaGetSymbolAddress((void**)&NS,    g_ns);

    const int CSM = CONV_STG_B * 3;               // 99840
    const int GSM = 67584;
    cudaFuncSetAttribute(conv_mma,  cudaFuncAttributeMaxDynamicSharedMemorySize, CSM);
    cudaFuncSetAttribute(gemm_qkv,  cudaFuncAttributeMaxDynamicSharedMemorySize, GSM);
    cudaFuncSetAttribute(gemm_proj, cudaFuncAttributeMaxDynamicSharedMemorySize, GSM);

    wprep_kernel<<<5632, 256>>>(w_iem, w_nem, w_q, w_k, w_v, w_proj, WCT, WT4);
    xT_kernel<<<dim3(2048, 8, 2), dim3(32, 32)>>>(x, Xh);

    conv_mma<<<dim3(512, 2, 4), 256, CSM>>>(Xh, WCT, Hc1, Hc2, PART);

    bnstats2a<<<dim3(2, 32), 256>>>(PART, PART2);
    bnstats2b<<<2, 256>>>(PART2, g_iem, b_iem, g_nem, b_nem, BNA, BNC);

    dwconv_t<<<dim3(65536, 2), 128>>>(Hc1, Hc2, BNA, BNC, w_idw, w_ndw,
                                      Hd1, Hd2, IS, NS);

    gemm_qkv<<<dim3(512, 2, 6), 256, GSM>>>(WT4, Hd1, Hd2, Xh, Hq, Hk, Hv);

    attn_mma<<<dim3(1024, 8, 2), 128>>>(Hq, Hk, Hv, IS, NS, temp, Ha);

    gemm_proj<<<dim3(512, 2, 2), 256, GSM>>>(WT4 + 3 * 65536, Ha, out);
}

// round 17
// speedup vs baseline: 1.1766x; 1.0542x over previous
#include <cuda_runtime.h>
#include <cuda_fp16.h>
#include <math.h>
#include <stdint.h>

#define HW 65536
#define NBUF (2*256*HW)

// ---------------- static scratch (all big intermediates fp16) ----------------
__device__ __half g_Xh[NBUF];       // x [b][px][c]
__device__ __half g_Hc1[NBUF];      // conv_iem out [r][c]
__device__ __half g_Hc2[NBUF];      // conv_nem out [r][c]
__device__ __half g_Hd1[NBUF];      // illum map [r][c]
__device__ __half g_Hd2[NBUF];      // noise map [r][c]
__device__ __half g_Hq[NBUF];       // q [r][c]
__device__ __half g_Hk[NBUF];       // k [r][c]
__device__ __half g_Hv[NBUF];       // v [r][c]
__device__ __half g_Ha[NBUF];       // attn out [r][c]
__device__ __half g_wct[2*589824];  // conv weights [m][tap][oc][c]
__device__ __half g_wt4[4*65536];   // 1x1 weights [m][oc][c]
__device__ float  g_part[1048576];  // bn partials [2][1024 cta][2][256 ch]
__device__ float  g_part2[32768];   // bn partials lvl2 [2][32][2][256]
__device__ float  g_bna[512];
__device__ float  g_bnc[512];
__device__ float  g_is[2*HW];
__device__ float  g_ns[2*HW];

// ---------------- helpers ----------------
__device__ __forceinline__ uint32_t smem_u32(const void* p) {
    uint32_t a;
    asm("{ .reg .u64 t; cvta.to.shared.u64 t, %1; cvt.u32.u64 %0, t; }" : "=r"(a) : "l"(p));
    return a;
}
__device__ __forceinline__ uint32_t f2h2(float a, float b) {
    __half2 h = __floats2half2_rn(a, b);
    return *(uint32_t*)&h;
}
__device__ __forceinline__ void h8_to_f(uint4 t, float* f) {
    const __half2* hp = (const __half2*)&t;
#pragma unroll
    for (int u = 0; u < 4; u++) {
        float2 ff = __half22float2(hp[u]);
        f[2*u] = ff.x; f[2*u+1] = ff.y;
    }
}
__device__ __forceinline__ void cpa16(uint32_t s, const void* g, uint32_t n) {
    asm volatile("cp.async.cg.shared.global [%0], [%1], 16, %2;"
                 :: "r"(s), "l"(g), "r"(n) : "memory");
}
#define CP_COMMIT()  asm volatile("cp.async.commit_group;" ::: "memory")
#define CP_WAIT2()   asm volatile("cp.async.wait_group 2;" ::: "memory")
#define CP_WAIT1()   asm volatile("cp.async.wait_group 1;" ::: "memory")
#define CP_WAIT0()   asm volatile("cp.async.wait_group 0;" ::: "memory")

// fp16 m16n8k16 mma, fp32 accumulate (family-portable HMMA)
__device__ __forceinline__ void mma16(float* d, const uint32_t* a, const uint32_t* b) {
    asm volatile("mma.sync.aligned.m16n8k16.row.col.f32.f16.f16.f32 "
        "{%0,%1,%2,%3}, {%4,%5,%6,%7}, {%8,%9}, {%0,%1,%2,%3};"
        : "+f"(d[0]), "+f"(d[1]), "+f"(d[2]), "+f"(d[3])
        : "r"(a[0]), "r"(a[1]), "r"(a[2]), "r"(a[3]), "r"(b[0]), "r"(b[1]));
}
// ldmatrix x4 (sm_75+, family-portable)
__device__ __forceinline__ void ldsm4(uint32_t* r, uint32_t a) {
    asm volatile("ldmatrix.sync.aligned.m8n8.x4.shared.b16 {%0,%1,%2,%3}, [%4];"
        : "=r"(r[0]), "=r"(r[1]), "=r"(r[2]), "=r"(r[3]) : "r"(a));
}
__device__ __forceinline__ void ldsm4t(uint32_t* r, uint32_t a) {
    asm volatile("ldmatrix.sync.aligned.m8n8.x4.trans.shared.b16 {%0,%1,%2,%3}, [%4];"
        : "=r"(r[0]), "=r"(r[1]), "=r"(r[2]), "=r"(r[3]) : "r"(a));
}

// ---------------- merged weight prep ----------------
__global__ void wprep_kernel(const float* __restrict__ w0, const float* __restrict__ w1,
                             const float* __restrict__ wq, const float* __restrict__ wk,
                             const float* __restrict__ wv, const float* __restrict__ wp,
                             __half* __restrict__ outc, __half* __restrict__ out1) {
    if (blockIdx.x < 4608) {
        int i = blockIdx.x * 256 + threadIdx.x;          // 2*589824
        int m = i / 589824;
        int r = i - m * 589824;
        int tap = r >> 16;
        int rem = r & 65535;
        int oc  = rem >> 8;
        int c   = rem & 255;
        const float* w = m ? w1 : w0;
        outc[i] = __float2half_rn(w[oc * 2304 + c * 9 + tap]);
    } else {
        int i = (blockIdx.x - 4608) * 256 + threadIdx.x; // 4*65536
        int m = i >> 16;
        int r = i & 65535;
        int o = r >> 8;
        int c = r & 255;
        const float* w = (m == 0) ? wq : (m == 1) ? wk : (m == 2) ? wv : wp;
        out1[i] = __float2half_rn(w[o * 256 + c]);
    }
}

// ---------------- x transpose: NCHW -> [b][px][c] fp16 (half2 stores) ----------------
__global__ void xT_kernel(const float* __restrict__ x, __half* __restrict__ xT) {
    __shared__ float t[32][33];
    int b  = blockIdx.z;
    int c0 = blockIdx.y * 32;
    int p0 = blockIdx.x * 32;
    int tx = threadIdx.x, ty = threadIdx.y;
    t[ty][tx] = x[(((size_t)((b << 8) + c0 + ty)) << 16) + p0 + tx];
    __syncthreads();
    int u = ty * 32 + tx;
    if (u < 512) {
        int r = u >> 4, cp = u & 15;
        __half2 hv = __floats2half2_rn(t[2*cp][r], t[2*cp + 1][r]);
        *(__half2*)(xT + (((size_t)((b << 16) + p0 + r)) << 8) + c0 + 2 * cp) = hv;
    }
}

// ---------------- 3x3 conv implicit GEMM (fp16 mma + ldmatrix), 3-stage,
//                  both convs in one launch, BN partials fused ----------------
#define CONV_XS_B  8704
#define CONV_STG_B 33280
__global__ void __launch_bounds__(256, 2) conv_mma(const __half* __restrict__ xT,
                                                   const __half* __restrict__ W2base,
                                                   __half* __restrict__ out1,
                                                   __half* __restrict__ out2,
                                                   float* __restrict__ part) {
    extern __shared__ char smc[];
    const int tid  = threadIdx.x;
    const int w    = tid >> 5, lane = tid & 31;
    const int g    = lane >> 2, tg = lane & 3;
    const int y    = blockIdx.x >> 1;
    const int p0   = (blockIdx.x & 1) << 7;
    const int oc0  = blockIdx.y << 7;
    const int m    = blockIdx.z >> 1;
    const int b    = blockIdx.z & 1;
    const __half* W2 = W2base + (size_t)m * 589824;
    __half* out = m ? out2 : out1;
    const int wm   = w >> 2, wn = w & 3;
    const uint32_t sm_u = smem_u32(smc);
    const int aRowB = wm * 64 + (lane & 15);
    const int bRowB = wn * 32 + ((lane >> 4) << 3) + (lane & 7);
    const uint32_t aQ = (uint32_t)(lane >> 4);
    const uint32_t bQ = (uint32_t)((lane >> 3) & 1);

    float acc[4][4][4];
#pragma unroll
    for (int mi = 0; mi < 4; mi++)
#pragma unroll
        for (int ni = 0; ni < 4; ni++)
#pragma unroll
            for (int r = 0; r < 4; r++) acc[mi][ni][r] = 0.f;

    auto do_load = [&](int step, int buf) {
        int cc = step / 3;
        int ky = step - cc * 3;
        int c0 = cc * 32;
        uint32_t xs = sm_u + buf * CONV_STG_B;
        uint32_t ws = xs + CONV_XS_B;
        int yin = y + ky - 1;
        bool yok = (unsigned)yin < 256u;
#pragma unroll
        for (int jj = 0; jj < 3; jj++) {
            int j = jj * 256 + tid;
            if (j < 520) {
                int r = j >> 2, q = j & 3;
                int xin = p0 + r - 1;
                bool ok = yok && ((unsigned)xin < 256u);
                const __half* src = ok
                    ? xT + ((((size_t)b << 16) + ((size_t)yin << 8) + xin) << 8) + c0 + q * 8
                    : xT;
                cpa16(xs + r * 64 + ((q ^ ((r >> 1) & 3)) << 4), src, ok ? 16u : 0u);
            }
        }
#pragma unroll
        for (int jj = 0; jj < 6; jj++) {
            int j = jj * 256 + tid;
            int row = j >> 2, q = j & 3;          // row = kx*128+oc
            int kx = row >> 7, oc = row & 127;
            int tap = ky * 3 + kx;
            cpa16(ws + row * 64 + ((q ^ ((row >> 1) & 3)) << 4),
                  W2 + (((size_t)(tap * 256 + oc0 + oc)) << 8) + c0 + q * 8, 16u);
        }
        CP_COMMIT();
    };

    auto do_compute = [&](int buf) {
        uint32_t xs = sm_u + buf * CONV_STG_B;
        uint32_t ws = xs + CONV_XS_B;
#pragma unroll
        for (int kx = 0; kx < 3; kx++) {
#pragma unroll
            for (int ks = 0; ks < 2; ks++) {
                uint32_t af[4][4];
#pragma unroll
                for (int mi = 0; mi < 4; mi++) {
                    int row = aRowB + mi * 16 + kx;
                    uint32_t q = (uint32_t)(ks * 2) + aQ;
                    ldsm4(af[mi], xs + row * 64 + ((q ^ ((row >> 1) & 3)) << 4));
                }
                uint32_t bf[4][2];
#pragma unroll
                for (int pn = 0; pn < 2; pn++) {
                    int row = kx * 128 + bRowB + pn * 16;
                    uint32_t q = (uint32_t)(ks * 2) + bQ;
                    uint32_t t[4];
                    ldsm4(t, ws + row * 64 + ((q ^ ((row >> 1) & 3)) << 4));
                    bf[2*pn][0]   = t[0]; bf[2*pn][1]   = t[1];
                    bf[2*pn+1][0] = t[2]; bf[2*pn+1][1] = t[3];
                }
#pragma unroll
                for (int mi = 0; mi < 4; mi++)
#pragma unroll
                    for (int ni = 0; ni < 4; ni++)
                        mma16(acc[mi][ni], af[mi], bf[ni]);
            }
        }
    };

    do_load(0, 0);
    do_load(1, 1);
    for (int s = 0; s < 24; s++) {
        if (s < 23) { CP_WAIT1(); } else { CP_WAIT0(); }
        __syncthreads();
        if (s + 2 < 24) do_load(s + 2, (s + 2) % 3);
        do_compute(s % 3);
    }
    __syncthreads();

    float* S = (float*)smc;     // 128*132*4 = 67584
#pragma unroll
    for (int mi = 0; mi < 4; mi++) {
        int px = wm * 64 + mi * 16 + g;
#pragma unroll
        for (int ni = 0; ni < 4; ni++) {
            int oc = wn * 32 + ni * 8 + 2 * tg;
            S[px * 132 + oc]           = acc[mi][ni][0];
            S[px * 132 + oc + 1]       = acc[mi][ni][1];
            S[(px + 8) * 132 + oc]     = acc[mi][ni][2];
            S[(px + 8) * 132 + oc + 1] = acc[mi][ni][3];
        }
    }
    __syncthreads();
#pragma unroll
    for (int it = 0; it < 16; it++) {
        int px = w + it * 8;
        float4 v = *(float4*)&S[px * 132 + lane * 4];
        uint2 o;
        o.x = f2h2(v.x, v.y);
        o.y = f2h2(v.z, v.w);
        *(uint2*)(out + (((size_t)((b << 16) + (y << 8) + p0 + px)) << 8) + oc0 + lane * 4) = o;
    }
    // fused BN partials
    float* R = (float*)(smc + 67584);
    {
        int ocl = tid & 127, half = tid >> 7;
        float s = 0.f, s2 = 0.f;
#pragma unroll 8
        for (int px = 0; px < 64; px++) {
            float v = S[(half * 64 + px) * 132 + ocl];
            s += v; s2 = fmaf(v, v, s2);
        }
        R[(half * 128 + ocl) * 2]     = s;
        R[(half * 128 + ocl) * 2 + 1] = s2;
    }
    __syncthreads();
    if (tid < 128) {
        float s  = R[tid * 2]     + R[(128 + tid) * 2];
        float s2 = R[tid * 2 + 1] + R[(128 + tid) * 2 + 1];
        size_t base = ((size_t)(m * 1024 + b * 512 + blockIdx.x) * 2) * 256 + oc0 + tid;
        part[base]       = s;
        part[base + 256] = s2;
    }
}

// ---------------- BN stats: two-stage parallel reduce ----------------
__global__ void bnstats2a(const float* __restrict__ part, float* __restrict__ part2) {
    int m = blockIdx.x, chunk = blockIdx.y;
    int c = threadIdx.x;
    float s = 0.f, s2 = 0.f;
    for (int r = 0; r < 32; r++) {
        size_t base = ((size_t)(m * 1024 + chunk * 32 + r) * 2) * 256;
        s  += part[base + c];
        s2 += part[base + 256 + c];
    }
    size_t ob = ((size_t)(m * 32 + chunk) * 2) * 256;
    part2[ob + c]       = s;
    part2[ob + 256 + c] = s2;
}

__global__ void bnstats2b(const float* __restrict__ part2,
                          const float* __restrict__ g1, const float* __restrict__ b1,
                          const float* __restrict__ g2, const float* __restrict__ b2,
                          float* __restrict__ pa, float* __restrict__ pc) {
    int m = blockIdx.x;
    const float* gamma = m ? g2 : g1;
    const float* beta  = m ? b2 : b1;
    int c = threadIdx.x;
    float s = 0.f, s2 = 0.f;
    for (int r = 0; r < 32; r++) {
        size_t base = ((size_t)(m * 32 + r) * 2) * 256;
        s  += part2[base + c];
        s2 += part2[base + 256 + c];
    }
    float mean = s  * (1.f / 131072.f);
    float var  = s2 * (1.f / 131072.f) - mean * mean;
    float a = gamma[c] * rsqrtf(var + 1e-5f);
    pa[m * 256 + c] = a;
    pc[m * 256 + c] = beta[c] - mean * a;
}

// ---------------- depthwise conv pair, half2 loads, 2ch x 4px per thread,
//                  BN+relu6 fused, channel-mean fused ----------------
__global__ void __launch_bounds__(128) dwconv_t(
                         const __half* __restrict__ in1, const __half* __restrict__ in2,
                         const float* __restrict__ pa, const float* __restrict__ pc,
                         const float* __restrict__ wd1, const float* __restrict__ wd2,
                         __half* __restrict__ out1, __half* __restrict__ out2,
                         float* __restrict__ mean1, float* __restrict__ mean2) {
    __shared__ float red[4][4];
    int m = blockIdx.y;
    const __half* in  = m ? in2 : in1;
    const float*  wdw = m ? wd2 : wd1;
    __half* out       = m ? out2 : out1;
    float* mean_out   = m ? mean2 : mean1;
    int j = blockIdx.x;          // rows 4j..4j+3 (same image row)
    int c2 = threadIdx.x;        // channel pair 0..127
    int r0 = j << 2;
    int p  = r0 & 65535;
    int y = p >> 8, xx = p & 255;          // xx multiple of 4
    size_t bb = (size_t)(r0 - p) << 8;
    float a0 = pa[m * 256 + 2 * c2],     cb0 = pc[m * 256 + 2 * c2];
    float a1 = pa[m * 256 + 2 * c2 + 1], cb1 = pc[m * 256 + 2 * c2 + 1];
    float w0[9], w1[9];
#pragma unroll
    for (int t = 0; t < 9; t++) {
        w0[t] = wdw[(2 * c2) * 9 + t];
        w1[t] = wdw[(2 * c2 + 1) * 9 + t];
    }
    float acc0[4] = {0.f, 0.f, 0.f, 0.f};
    float acc1[4] = {0.f, 0.f, 0.f, 0.f};
#pragma unroll
    for (int ky = 0; ky < 3; ky++) {
        int yy = y + ky - 1;
        if ((unsigned)yy >= 256u) continue;
        float v0[6], v1[6];
#pragma unroll
        for (int dx = 0; dx < 6; dx++) {
            int xv = xx + dx - 1;
            bool ok = (unsigned)xv < 256u;
            float2 f = {0.f, 0.f};
            if (ok) {
                __half2 hv = *(const __half2*)(in + (bb + (size_t)((yy << 8) + xv) * 256) + 2 * c2);
                f = __half22float2(hv);
            }
            float t0 = fminf(fmaxf(f.x * a0 + cb0, 0.f), 6.f);
            float t1 = fminf(fmaxf(f.y * a1 + cb1, 0.f), 6.f);
            v0[dx] = ok ? t0 : 0.f;
            v1[dx] = ok ? t1 : 0.f;
        }
#pragma unroll
        for (int px = 0; px < 4; px++) {
            acc0[px] = fmaf(w0[ky*3+0], v0[px],     acc0[px]);
            acc0[px] = fmaf(w0[ky*3+1], v0[px + 1], acc0[px]);
            acc0[px] = fmaf(w0[ky*3+2], v0[px + 2], acc0[px]);
            acc1[px] = fmaf(w1[ky*3+0], v1[px],     acc1[px]);
            acc1[px] = fmaf(w1[ky*3+1], v1[px + 1], acc1[px]);
            acc1[px] = fmaf(w1[ky*3+2], v1[px + 2], acc1[px]);
        }
    }
#pragma unroll
    for (int px = 0; px < 4; px++)
        *(__half2*)(out + (size_t)(r0 + px) * 256 + 2 * c2) = __floats2half2_rn(acc0[px], acc1[px]);

    float s[4];
#pragma unroll
    for (int px = 0; px < 4; px++) s[px] = acc0[px] + acc1[px];
#pragma unroll
    for (int off = 16; off; off >>= 1) {
#pragma unroll
        for (int px = 0; px < 4; px++)
            s[px] += __shfl_xor_sync(0xffffffffu, s[px], off);
    }
    if ((c2 & 31) == 0) {
#pragma unroll
        for (int px = 0; px < 4; px++) red[c2 >> 5][px] = s[px];
    }
    __syncthreads();
    if (c2 < 4) {
        float t = red[0][c2] + red[1][c2] + red[2][c2] + red[3][c2];
        mean_out[r0 + c2] = t * (1.f / 256.f);
    }
}

// ---------------- 1x1 GEMM core (fp16 mma + ldmatrix), 4-stage/3-deep ----------------
#define GEMM_XS_B  8192
#define GEMM_STG_B 16384
__device__ __forceinline__ void gemm_core(const __half* __restrict__ wt,
                                          const __half* __restrict__ in,
                                          uint32_t sm_u,
                                          int tid, int lane, int wm, int wn,
                                          size_t r0, int oc0, float acc[4][4][4]) {
    const int aRowB = wm * 64 + (lane & 15);
    const int bRowB = wn * 32 + ((lane >> 4) << 3) + (lane & 7);
    const uint32_t aQ = (uint32_t)(lane >> 4);
    const uint32_t bQ = (uint32_t)((lane >> 3) & 1);

    auto do_load = [&](int cc, int buf) {
        int c0 = cc * 32;
        uint32_t xs = sm_u + buf * GEMM_STG_B;
        uint32_t ws = xs + GEMM_XS_B;
#pragma unroll
        for (int jj = 0; jj < 2; jj++) {
            int j = jj * 256 + tid;
            int r = j >> 2, q = j & 3;
            cpa16(xs + r * 64 + ((q ^ ((r >> 1) & 3)) << 4),
                  in + (r0 + r) * 256 + c0 + q * 8, 16u);
        }
#pragma unroll
        for (int jj = 0; jj < 2; jj++) {
            int j = jj * 256 + tid;
            int r = j >> 2, q = j & 3;
            cpa16(ws + r * 64 + ((q ^ ((r >> 1) & 3)) << 4),
                  wt + (size_t)(oc0 + r) * 256 + c0 + q * 8, 16u);
        }
        CP_COMMIT();
    };

    auto do_compute = [&](int buf) {
        uint32_t xs = sm_u + buf * GEMM_STG_B;
        uint32_t ws = xs + GEMM_XS_B;
#pragma unroll
        for (int ks = 0; ks < 2; ks++) {
            uint32_t af[4][4];
#pragma unroll
            for (int mi = 0; mi < 4; mi++) {
                int row = aRowB + mi * 16;
                uint32_t q = (uint32_t)(ks * 2) + aQ;
                ldsm4(af[mi], xs + row * 64 + ((q ^ ((row >> 1) & 3)) << 4));
            }
            uint32_t bf[4][2];
#pragma unroll
            for (int pn = 0; pn < 2; pn++) {
                int row = bRowB + pn * 16;
                uint32_t q = (uint32_t)(ks * 2) + bQ;
                uint32_t t[4];
                ldsm4(t, ws + row * 64 + ((q ^ ((row >> 1) & 3)) << 4));
                bf[2*pn][0]   = t[0]; bf[2*pn][1]   = t[1];
                bf[2*pn+1][0] = t[2]; bf[2*pn+1][1] = t[3];
            }
#pragma unroll
            for (int mi = 0; mi < 4; mi++)
#pragma unroll
                for (int ni = 0; ni < 4; ni++)
                    mma16(acc[mi][ni], af[mi], bf[ni]);
        }
    };

    do_load(0, 0);
    do_load(1, 1);
    do_load(2, 2);
    for (int s = 0; s < 8; s++) {
        if (s < 6) { CP_WAIT2(); } else if (s == 6) { CP_WAIT1(); } else { CP_WAIT0(); }
        __syncthreads();
        if (s + 3 < 8) do_load(s + 3, (s + 3) & 3);
        do_compute(s & 3);
    }
    __syncthreads();
}

// q/k/v in one launch: grid (512, 2, 6); outputs plain [r][c] fp16
__global__ void __launch_bounds__(256, 2) gemm_qkv(const __half* __restrict__ wtb,
                                                   const __half* __restrict__ in1,
                                                   const __half* __restrict__ in2,
                                                   const __half* __restrict__ in3,
                                                   __half* __restrict__ o1,
                                                   __half* __restrict__ o2,
                                                   __half* __restrict__ o3) {
    extern __shared__ char smc[];
    const int tid  = threadIdx.x;
    const int w    = tid >> 5, lane = tid & 31;
    const int g    = lane >> 2, tg = lane & 3;
    const int tile = blockIdx.x;
    const int oc0  = blockIdx.y << 7;
    const int which = blockIdx.z >> 1;
    const int b    = blockIdx.z & 1;
    const int wm   = w >> 2, wn = w & 3;
    const __half* wt = wtb + (size_t)which * 65536;
    const __half* in = (which == 0) ? in1 : (which == 1) ? in2 : in3;
    __half* out      = (which == 0) ? o1  : (which == 1) ? o2  : o3;
    const uint32_t sm_u = smem_u32(smc);
    const size_t r0 = ((size_t)b << 16) + (size_t)tile * 128;

    float acc[4][4][4];
#pragma unroll
    for (int mi = 0; mi < 4; mi++)
#pragma unroll
        for (int ni = 0; ni < 4; ni++)
#pragma unroll
            for (int r = 0; r < 4; r++) acc[mi][ni][r] = 0.f;

    gemm_core(wt, in, sm_u, tid, lane, wm, wn, r0, oc0, acc);

    float* S = (float*)smc;
#pragma unroll
    for (int mi = 0; mi < 4; mi++) {
        int px = wm * 64 + mi * 16 + g;
#pragma unroll
        for (int ni = 0; ni < 4; ni++) {
            int oc = wn * 32 + ni * 8 + 2 * tg;
            S[px * 132 + oc]           = acc[mi][ni][0];
            S[px * 132 + oc + 1]       = acc[mi][ni][1];
            S[(px + 8) * 132 + oc]     = acc[mi][ni][2];
            S[(px + 8) * 132 + oc + 1] = acc[mi][ni][3];
        }
    }
    __syncthreads();
#pragma unroll
    for (int it = 0; it < 16; it++) {
        int px = w + it * 8;
        float4 v = *(float4*)&S[px * 132 + lane * 4];
        uint2 o;
        o.x = f2h2(v.x, v.y);
        o.y = f2h2(v.z, v.w);
        *(uint2*)(out + ((r0 + px) << 8) + oc0 + lane * 4) = o;
    }
}

// proj: NCHW fp32 out
__global__ void __launch_bounds__(256, 2) gemm_proj(const __half* __restrict__ wt,
                                                    const __half* __restrict__ in,
                                                    float* __restrict__ out) {
    extern __shared__ char smc[];
    const int tid  = threadIdx.x;
    const int w    = tid >> 5, lane = tid & 31;
    const int g    = lane >> 2, tg = lane & 3;
    const int tile = blockIdx.x;
    const int oc0  = blockIdx.y << 7;
    const int b    = blockIdx.z;
    const int wm   = w >> 2, wn = w & 3;
    const uint32_t sm_u = smem_u32(smc);
    const size_t r0 = ((size_t)b << 16) + (size_t)tile * 128;

    float acc[4][4][4];
#pragma unroll
    for (int mi = 0; mi < 4; mi++)
#pragma unroll
        for (int ni = 0; ni < 4; ni++)
#pragma unroll
            for (int r = 0; r < 4; r++) acc[mi][ni][r] = 0.f;

    gemm_core(wt, in, sm_u, tid, lane, wm, wn, r0, oc0, acc);

    float* S = (float*)smc;
#pragma unroll
    for (int mi = 0; mi < 4; mi++) {
        int px = wm * 64 + mi * 16 + g;
#pragma unroll
        for (int ni = 0; ni < 4; ni++) {
            int oc = wn * 32 + ni * 8 + 2 * tg;
            S[oc * 132 + px]           = acc[mi][ni][0];
            S[(oc + 1) * 132 + px]     = acc[mi][ni][1];
            S[oc * 132 + px + 8]       = acc[mi][ni][2];
            S[(oc + 1) * 132 + px + 8] = acc[mi][ni][3];
        }
    }
    __syncthreads();
#pragma unroll
    for (int it = 0; it < 16; it++) {
        int oc = w + it * 8;
        float4 v = *(float4*)&S[oc * 132 + lane * 4];
        *(float4*)&out[(((size_t)(b * 256 + oc0 + oc)) << 16) + tile * 128 + lane * 4] = v;
    }
}

// ---------------- windowed attention on tensor cores ----------------
// 1 block = 1 window, 128 threads = 4 warps (warp w owns q-rows 16w..16w+15).
// V stored row-major like K; PV B-fragments via ldmatrix.trans.
__global__ void __launch_bounds__(128) attn_mma(const __half* __restrict__ q,
                                                const __half* __restrict__ k,
                                                const __half* __restrict__ v,
                                                const float* __restrict__ is,
                                                const float* __restrict__ ns,
                                                const float* __restrict__ temp,
                                                __half* __restrict__ out) {
    __shared__ __align__(16) __half Qs[64 * 40];   // 80B rows
    __shared__ __align__(16) __half Ks[64 * 40];
    __shared__ __align__(16) __half Vs[64 * 40];   // [j][d], 80B rows
    const int t   = threadIdx.x;
    const int win = blockIdx.x;
    const int h   = blockIdx.y;
    const int b   = blockIdx.z;
    const int w   = t >> 5, lane = t & 31;
    const int g   = lane >> 2, tg = lane & 3;

    // ---- load + scale phase: 2 threads per row ----
    {
        int i = t >> 1, hp = t & 1;
        int y = ((win >> 5) << 3) + (i >> 3);
        int x = ((win & 31) << 3) + (i & 7);
        int pidx = (b << 16) + (y << 8) + x;
        size_t rc = ((size_t)pidx << 8) + (h << 5) + hp * 16;
        float qf[16], kf[16];
        {
            const uint4* p4 = (const uint4*)(q + rc);
            h8_to_f(p4[0], qf); h8_to_f(p4[1], qf + 8);
        }
        {
            const uint4* p4 = (const uint4*)(k + rc);
            h8_to_f(p4[0], kf); h8_to_f(p4[1], kf + 8);
        }
        {
            const uint4* p4 = (const uint4*)(v + rc);
            uint4* vd = (uint4*)(Vs + i * 40 + hp * 16);
            vd[0] = p4[0];
            vd[1] = p4[1];
        }
        float qn = 0.f, kn = 0.f;
#pragma unroll
        for (int u = 0; u < 16; u++) {
            qn = fmaf(qf[u], qf[u], qn);
            kn = fmaf(kf[u], kf[u], kn);
        }
        qn += __shfl_xor_sync(0xffffffffu, qn, 1);
        kn += __shfl_xor_sync(0xffffffffu, kn, 1);
        float nsv = ns[pidx];
        float kmul = fminf(fmaxf(1.f - nsv, 0.f), 1.f) / fmaxf(sqrtf(kn), 1e-12f);
        float qmul = (1.f + is[pidx]) / fmaxf(sqrtf(qn), 1e-12f)
                   * 0.17677669529663687f * temp[h];
        __half2* qrow = (__half2*)(Qs + i * 40 + hp * 16);
        __half2* krow = (__half2*)(Ks + i * 40 + hp * 16);
#pragma unroll
        for (int u = 0; u < 8; u++) {
            qrow[u] = __floats2half2_rn(qf[2*u] * qmul, qf[2*u+1] * qmul);
            krow[u] = __floats2half2_rn(kf[2*u] * kmul, kf[2*u+1] * kmul);
        }
    }
    __syncthreads();

    const uint32_t qs_u = smem_u32(Qs);
    const uint32_t ks_u = smem_u32(Ks);
    const uint32_t vs_u = smem_u32(Vs);

    // ---- QK^T: M=64 N=64 K=32 ----
    float s[8][4];
#pragma unroll
    for (int ni = 0; ni < 8; ni++)
#pragma unroll
        for (int r = 0; r < 4; r++) s[ni][r] = 0.f;
#pragma unroll
    for (int ks = 0; ks < 2; ks++) {
        uint32_t af[4];
        ldsm4(af, qs_u + (16 * w + (lane & 15)) * 80 + ks * 32 + (lane >> 4) * 16);
#pragma unroll
        for (int pn = 0; pn < 4; pn++) {
            uint32_t tt[4];
            ldsm4(tt, ks_u + (pn * 16 + ((lane >> 4) << 3) + (lane & 7)) * 80
                       + ks * 32 + ((lane >> 3) & 1) * 16);
            mma16(s[2*pn],     af, tt);
            mma16(s[2*pn + 1], af, tt + 2);
        }
    }

    // ---- softmax in fragments (rows g, g+8 of warp block) ----
    float mx0 = -1e30f, mx1 = -1e30f;
#pragma unroll
    for (int ni = 0; ni < 8; ni++) {
        mx0 = fmaxf(mx0, fmaxf(s[ni][0], s[ni][1]));
        mx1 = fmaxf(mx1, fmaxf(s[ni][2], s[ni][3]));
    }
    mx0 = fmaxf(mx0, __shfl_xor_sync(0xffffffffu, mx0, 1));
    mx0 = fmaxf(mx0, __shfl_xor_sync(0xffffffffu, mx0, 2));
    mx1 = fmaxf(mx1, __shfl_xor_sync(0xffffffffu, mx1, 1));
    mx1 = fmaxf(mx1, __shfl_xor_sync(0xffffffffu, mx1, 2));
    float sum0 = 0.f, sum1 = 0.f;
#pragma unroll
    for (int ni = 0; ni < 8; ni++) {
        s[ni][0] = __expf(s[ni][0] - mx0);
        s[ni][1] = __expf(s[ni][1] - mx0);
        s[ni][2] = __expf(s[ni][2] - mx1);
        s[ni][3] = __expf(s[ni][3] - mx1);
        sum0 += s[ni][0] + s[ni][1];
        sum1 += s[ni][2] + s[ni][3];
    }
    sum0 += __shfl_xor_sync(0xffffffffu, sum0, 1);
    sum0 += __shfl_xor_sync(0xffffffffu, sum0, 2);
    sum1 += __shfl_xor_sync(0xffffffffu, sum1, 1);
    sum1 += __shfl_xor_sync(0xffffffffu, sum1, 2);
    float inv0 = 1.f / sum0, inv1 = 1.f / sum1;

    // ---- P x V: M=64 N=32 K=64 (P repacked; V via ldsm.trans on [j][d]) ----
    float o[4][4];
#pragma unroll
    for (int nd = 0; nd < 4; nd++)
#pragma unroll
        for (int r = 0; r < 4; r++) o[nd][r] = 0.f;
#pragma unroll
    for (int s4 = 0; s4 < 4; s4++) {
        uint32_t ap[4];
        ap[0] = f2h2(s[2*s4][0],     s[2*s4][1]);
        ap[1] = f2h2(s[2*s4][2],     s[2*s4][3]);
        ap[2] = f2h2(s[2*s4 + 1][0], s[2*s4 + 1][1]);
        ap[3] = f2h2(s[2*s4 + 1][2], s[2*s4 + 1][3]);
        uint32_t rowoff = (uint32_t)((s4 * 16 + ((lane >> 3) & 1) * 8 + (lane & 7)) * 80
                                     + (lane >> 4) * 16);
        uint32_t tt[4];
        ldsm4t(tt, vs_u + rowoff);
        mma16(o[0], ap, tt);
        mma16(o[1], ap, tt + 2);
        ldsm4t(tt, vs_u + rowoff + 32);
        mma16(o[2], ap, tt);
        mma16(o[3], ap, tt + 2);
    }

    // ---- stage output in smem (reuse Qs: own rows only), coalesced store ----
    __half2* Os = (__half2*)Qs;
#pragma unroll
    for (int nd = 0; nd < 4; nd++) {
        int col2 = (nd * 8 + 2 * tg) >> 1;
        Os[(16 * w + g)     * 20 + col2] = __floats2half2_rn(o[nd][0] * inv0, o[nd][1] * inv0);
        Os[(16 * w + g + 8) * 20 + col2] = __floats2half2_rn(o[nd][2] * inv1, o[nd][3] * inv1);
    }
    __syncthreads();
    {
        int i = t >> 1, hp = t & 1;
        int y = ((win >> 5) << 3) + (i >> 3);
        int x = ((win & 31) << 3) + (i & 7);
        int pidx = (b << 16) + (y << 8) + x;
        size_t rc = ((size_t)pidx << 8) + (h << 5) + hp * 16;
        const uint4* src = (const uint4*)(Qs + i * 40 + hp * 16);
        uint4* dst = (uint4*)(out + rc);
        dst[0] = src[0];
        dst[1] = src[1];
    }
}

// ---------------- launch ----------------
extern "C" void kernel_launch(void* const* d_in, const int* in_sizes, int n_in,
                              void* d_out, int out_size) {
    const float* x      = (const float*)d_in[0];
    const float* w_iem  = (const float*)d_in[1];
    const float* g_iem  = (const float*)d_in[2];
    const float* b_iem  = (const float*)d_in[3];
    const float* w_nem  = (const float*)d_in[4];
    const float* g_nem  = (const float*)d_in[5];
    const float* b_nem  = (const float*)d_in[6];
    const float* w_idw  = (const float*)d_in[7];
    const float* w_ndw  = (const float*)d_in[8];
    const float* w_q    = (const float*)d_in[9];
    const float* w_k    = (const float*)d_in[10];
    const float* w_v    = (const float*)d_in[11];
    const float* w_proj = (const float*)d_in[12];
    const float* temp   = (const float*)d_in[13];
    float* out = (float*)d_out;

    float *PART, *PART2, *BNA, *BNC, *IS, *NS;
    __half *Xh, *Hc1, *Hc2, *Hd1, *Hd2, *Hq, *Hk, *Hv, *Ha, *WCT, *WT4;
    cudaGetSymbolAddress((void**)&Xh,    g_Xh);
    cudaGetSymbolAddress((void**)&Hc1,   g_Hc1);
    cudaGetSymbolAddress((void**)&Hc2,   g_Hc2);
    cudaGetSymbolAddress((void**)&Hd1,   g_Hd1);
    cudaGetSymbolAddress((void**)&Hd2,   g_Hd2);
    cudaGetSymbolAddress((void**)&Hq,    g_Hq);
    cudaGetSymbolAddress((void**)&Hk,    g_Hk);
    cudaGetSymbolAddress((void**)&Hv,    g_Hv);
    cudaGetSymbolAddress((void**)&Ha,    g_Ha);
    cudaGetSymbolAddress((void**)&WCT,   g_wct);
    cudaGetSymbolAddress((void**)&WT4,   g_wt4);
    cudaGetSymbolAddress((void**)&PART,  g_part);
    cudaGetSymbolAddress((void**)&PART2, g_part2);
    cudaGetSymbolAddress((void**)&BNA,   g_bna);
    cudaGetSymbolAddress((void**)&BNC,   g_bnc);
    cudaGetSymbolAddress((void**)&IS,    g_is);
    cudaGetSymbolAddress((void**)&NS,    g_ns);

    const int CSM = CONV_STG_B * 3;               // 99840
    const int GSM = 67584;
    cudaFuncSetAttribute(conv_mma,  cudaFuncAttributeMaxDynamicSharedMemorySize, CSM);
    cudaFuncSetAttribute(gemm_qkv,  cudaFuncAttributeMaxDynamicSharedMemorySize, GSM);
    cudaFuncSetAttribute(gemm_proj, cudaFuncAttributeMaxDynamicSharedMemorySize, GSM);

    wprep_kernel<<<5632, 256>>>(w_iem, w_nem, w_q, w_k, w_v, w_proj, WCT, WT4);
    xT_kernel<<<dim3(2048, 8, 2), dim3(32, 32)>>>(x, Xh);

    conv_mma<<<dim3(512, 2, 4), 256, CSM>>>(Xh, WCT, Hc1, Hc2, PART);

    bnstats2a<<<dim3(2, 32), 256>>>(PART, PART2);
    bnstats2b<<<2, 256>>>(PART2, g_iem, b_iem, g_nem, b_nem, BNA, BNC);

    dwconv_t<<<dim3(32768, 2), 128>>>(Hc1, Hc2, BNA, BNC, w_idw, w_ndw,
                                      Hd1, Hd2, IS, NS);

    gemm_qkv<<<dim3(512, 2, 6), 256, GSM>>>(WT4, Hd1, Hd2, Xh, Hq, Hk, Hv);

    attn_mma<<<dim3(1024, 8, 2), 128>>>(Hq, Hk, Hv, IS, NS, temp, Ha);

    gemm_proj<<<dim3(512, 2, 2), 256, GSM>>>(WT4 + 3 * 65536, Ha, out);
}